// round 2
// baseline (speedup 1.0000x reference)
#include <cuda_runtime.h>

// Problem sizes (fixed per reference)
#define B_    4096
#define I_    4
#define H_    2048
#define TWOH  4096
#define ID_   8
#define KTOT  (ID_ * TWOH)   // 32768

// Scratch (allocation-free rule: __device__ globals)
__device__ float g_gates[(size_t)B_ * TWOH];  // [B, 4096] : g1 | g2 (pre-activation)
__device__ float g_merge[(size_t)B_ * H_];    // [B, 2048] : s @ Wmerge

// ---------------------------------------------------------------------------
// Gates GEMM: C[m,n] = sum_k z[m,k] * Wc[k,n]
//   z[m, i*4096+j] = xcat[m,i] * s[m,j]
//   Wc[k, n]       = (n < 2048 ? W1 : W2)[i, j, n % 2048]
// Tiles: BM=128, BN=128, BK=16; 256 threads; 8x8 per-thread microtile.
// ---------------------------------------------------------------------------
__global__ __launch_bounds__(256, 2) void gates_gemm(
    const float* __restrict__ x0, const float* __restrict__ x1,
    const float* __restrict__ h0, const float* __restrict__ h1,
    const float* __restrict__ W1, const float* __restrict__ W2)
{
    constexpr int BM = 128, BN = 128, BK = 16;
    __shared__ float As[BK][BM];
    __shared__ float Bs[BK][BN];

    const int tid = threadIdx.x;
    const int m0  = blockIdx.y * BM;
    const int n0  = blockIdx.x * BN;

    const float* Wbase = (n0 < H_) ? W1 : W2;
    const int nW = n0 & (H_ - 1);

    // A loader: thread -> (row a_m, k-chunk a_k of 8)
    const int a_m = tid >> 1;            // 0..127
    const int a_k = (tid & 1) * 8;       // 0 or 8
    const int gm  = m0 + a_m;

    // B loader: thread -> (row b_k and b_k+8, 4 consecutive n)
    const int b_k = tid >> 5;            // 0..7
    const int b_n = (tid & 31) * 4;      // 0..124

    const int ty = tid >> 4;             // 0..15  -> rows ty*8..ty*8+7
    const int tx = tid & 15;             // 0..15  -> cols tx*4..+3 and 64+tx*4..+3

    float acc[8][8];
#pragma unroll
    for (int u = 0; u < 8; u++)
#pragma unroll
        for (int v = 0; v < 8; v++) acc[u][v] = 0.f;

    for (int kk = 0; kk < KTOT; kk += BK) {
        const int i  = kk >> 12;              // 0..7 (constant within tile)
        const int j0 = kk & (TWOH - 1);       // multiple of 16

        // ---- load A tile: s(m, j0..j0+15) scaled by xcat(m, i)
        {
            const float xs = (i < I_) ? x0[gm * I_ + i] : x1[gm * I_ + (i - I_)];
            const float* srow = (j0 < H_) ? (h0 + (size_t)gm * H_ + j0)
                                          : (h1 + (size_t)gm * H_ + (j0 - H_));
            float4 sa = *(const float4*)(srow + a_k);
            float4 sb = *(const float4*)(srow + a_k + 4);
            As[a_k + 0][a_m] = sa.x * xs;
            As[a_k + 1][a_m] = sa.y * xs;
            As[a_k + 2][a_m] = sa.z * xs;
            As[a_k + 3][a_m] = sa.w * xs;
            As[a_k + 4][a_m] = sb.x * xs;
            As[a_k + 5][a_m] = sb.y * xs;
            As[a_k + 6][a_m] = sb.z * xs;
            As[a_k + 7][a_m] = sb.w * xs;
        }

        // ---- load B tile: W[i, j0+k, nW + b_n .. +3], rows b_k and b_k+8
        {
            const float* wrow = Wbase + (size_t)i * TWOH * H_ + (size_t)j0 * H_ + nW;
#pragma unroll
            for (int r = 0; r < 2; r++) {
                const int k = b_k + r * 8;
                float4 w4 = *(const float4*)(wrow + (size_t)k * H_ + b_n);
                *(float4*)&Bs[k][b_n] = w4;
            }
        }
        __syncthreads();

#pragma unroll
        for (int k = 0; k < BK; k++) {
            float a[8], b[8];
            *(float4*)(a)     = *(const float4*)&As[k][ty * 8];
            *(float4*)(a + 4) = *(const float4*)&As[k][ty * 8 + 4];
            *(float4*)(b)     = *(const float4*)&Bs[k][tx * 4];
            *(float4*)(b + 4) = *(const float4*)&Bs[k][64 + tx * 4];
#pragma unroll
            for (int u = 0; u < 8; u++)
#pragma unroll
                for (int v = 0; v < 8; v++)
                    acc[u][v] += a[u] * b[v];
        }
        __syncthreads();
    }

    // ---- store to scratch
#pragma unroll
    for (int u = 0; u < 8; u++) {
        const size_t crow = (size_t)(m0 + ty * 8 + u) * TWOH + n0;
        float4 c0 = make_float4(acc[u][0], acc[u][1], acc[u][2], acc[u][3]);
        float4 c1 = make_float4(acc[u][4], acc[u][5], acc[u][6], acc[u][7]);
        *(float4*)(g_gates + crow + tx * 4)      = c0;
        *(float4*)(g_gates + crow + 64 + tx * 4) = c1;
    }
}

// ---------------------------------------------------------------------------
// Merge GEMM: g_merge[m,n] = sum_j s[m,j] * Wmerge[j,n]   (K = 4096, N = 2048)
// ---------------------------------------------------------------------------
__global__ __launch_bounds__(256, 2) void merge_gemm(
    const float* __restrict__ h0, const float* __restrict__ h1,
    const float* __restrict__ Wm)
{
    constexpr int BM = 128, BN = 128, BK = 16;
    __shared__ float As[BK][BM];
    __shared__ float Bs[BK][BN];

    const int tid = threadIdx.x;
    const int m0  = blockIdx.y * BM;
    const int n0  = blockIdx.x * BN;

    const int a_m = tid >> 1;
    const int a_k = (tid & 1) * 8;
    const int gm  = m0 + a_m;

    const int b_k = tid >> 5;
    const int b_n = (tid & 31) * 4;

    const int ty = tid >> 4;
    const int tx = tid & 15;

    float acc[8][8];
#pragma unroll
    for (int u = 0; u < 8; u++)
#pragma unroll
        for (int v = 0; v < 8; v++) acc[u][v] = 0.f;

    for (int j0 = 0; j0 < TWOH; j0 += BK) {
        {
            const float* srow = (j0 < H_) ? (h0 + (size_t)gm * H_ + j0)
                                          : (h1 + (size_t)gm * H_ + (j0 - H_));
            float4 sa = *(const float4*)(srow + a_k);
            float4 sb = *(const float4*)(srow + a_k + 4);
            As[a_k + 0][a_m] = sa.x;
            As[a_k + 1][a_m] = sa.y;
            As[a_k + 2][a_m] = sa.z;
            As[a_k + 3][a_m] = sa.w;
            As[a_k + 4][a_m] = sb.x;
            As[a_k + 5][a_m] = sb.y;
            As[a_k + 6][a_m] = sb.z;
            As[a_k + 7][a_m] = sb.w;
        }
        {
            const float* wrow = Wm + (size_t)j0 * H_ + n0;
#pragma unroll
            for (int r = 0; r < 2; r++) {
                const int k = b_k + r * 8;
                float4 w4 = *(const float4*)(wrow + (size_t)k * H_ + b_n);
                *(float4*)&Bs[k][b_n] = w4;
            }
        }
        __syncthreads();

#pragma unroll
        for (int k = 0; k < BK; k++) {
            float a[8], b[8];
            *(float4*)(a)     = *(const float4*)&As[k][ty * 8];
            *(float4*)(a + 4) = *(const float4*)&As[k][ty * 8 + 4];
            *(float4*)(b)     = *(const float4*)&Bs[k][tx * 4];
            *(float4*)(b + 4) = *(const float4*)&Bs[k][64 + tx * 4];
#pragma unroll
            for (int u = 0; u < 8; u++)
#pragma unroll
                for (int v = 0; v < 8; v++)
                    acc[u][v] += a[u] * b[v];
        }
        __syncthreads();
    }

#pragma unroll
    for (int u = 0; u < 8; u++) {
        const size_t crow = (size_t)(m0 + ty * 8 + u) * H_ + n0;
        float4 c0 = make_float4(acc[u][0], acc[u][1], acc[u][2], acc[u][3]);
        float4 c1 = make_float4(acc[u][4], acc[u][5], acc[u][6], acc[u][7]);
        *(float4*)(g_merge + crow + tx * 4)      = c0;
        *(float4*)(g_merge + crow + 64 + tx * 4) = c1;
    }
}

// ---------------------------------------------------------------------------
// Epilogue: new = sigmoid(g2+b2) * tanh(g1+b1) + (1-sigmoid(g2+b2)) * merge
// Written twice (output tuple is (new_state, new_state)).
// ---------------------------------------------------------------------------
__global__ __launch_bounds__(256) void epilogue_kernel(
    const float* __restrict__ b1, const float* __restrict__ b2,
    float* __restrict__ out)
{
    const size_t idx = (size_t)blockIdx.x * blockDim.x + threadIdx.x;  // < B_*H_
    const int n = (int)(idx & (H_ - 1));
    const size_t m = idx >> 11;

    const float g1 = g_gates[m * TWOH + n];
    const float g2 = g_gates[m * TWOH + H_ + n];
    const float mv = g_merge[idx];

    const float st = tanhf(g1 + b1[n]);
    const float u  = 1.0f / (1.0f + __expf(-(g2 + b2[n])));
    const float ns = u * st + (1.0f - u) * mv;

    out[idx] = ns;
    out[idx + (size_t)B_ * H_] = ns;
}

// ---------------------------------------------------------------------------
extern "C" void kernel_launch(void* const* d_in, const int* in_sizes, int n_in,
                              void* d_out, int out_size)
{
    const float* x0 = (const float*)d_in[0];
    const float* x1 = (const float*)d_in[1];
    const float* h0 = (const float*)d_in[2];
    const float* h1 = (const float*)d_in[3];
    const float* W1 = (const float*)d_in[4];
    const float* b1 = (const float*)d_in[5];
    const float* W2 = (const float*)d_in[6];
    const float* b2 = (const float*)d_in[7];
    const float* Wm = (const float*)d_in[8];
    float* out = (float*)d_out;

    // Gates GEMM: grid (N-tiles = 4096/128 = 32, M-tiles = 4096/128 = 32)
    dim3 g1grid(TWOH / 128, B_ / 128);
    gates_gemm<<<g1grid, 256>>>(x0, x1, h0, h1, W1, W2);

    // Merge GEMM: grid (2048/128 = 16, 32)
    dim3 g2grid(H_ / 128, B_ / 128);
    merge_gemm<<<g2grid, 256>>>(h0, h1, Wm);

    // Epilogue over B*H elements
    const size_t total = (size_t)B_ * H_;
    epilogue_kernel<<<(unsigned)(total / 256), 256>>>(b1, b2, out);
}

// round 4
// speedup vs baseline: 3.1254x; 3.1254x over previous
#include <cuda_runtime.h>
#include <cstdint>

#define B_    4096
#define H_    2048
#define TWOH  4096

// scratch
__device__ float g_gates[(size_t)B_ * TWOH];  // [B, 4096] : g1 | g2
__device__ float g_merge[(size_t)B_ * H_];    // [B, 2048]

// ---------------- helpers ----------------
__device__ __forceinline__ uint32_t smem_u32(const void* p) {
    uint32_t a;
    asm("{ .reg .u64 t; cvta.to.shared.u64 t, %1; cvt.u32.u64 %0, t; }" : "=r"(a) : "l"(p));
    return a;
}
__device__ __forceinline__ uint32_t f2tf(float x) {
    uint32_t r; asm("cvt.rna.tf32.f32 %0, %1;" : "=r"(r) : "f"(x)); return r;
}
__device__ __forceinline__ void cpa16(uint32_t dst, const void* src) {
    asm volatile("cp.async.cg.shared.global [%0], [%1], 16;" :: "r"(dst), "l"(src));
}
#define CP_COMMIT() asm volatile("cp.async.commit_group;")
#define CP_WAIT1()  asm volatile("cp.async.wait_group 1;")
#define CP_WAIT0()  asm volatile("cp.async.wait_group 0;")

__device__ __forceinline__ void mma8(float* c, const uint32_t* a, const uint32_t* b) {
    asm volatile(
        "mma.sync.aligned.m16n8k8.row.col.f32.tf32.tf32.f32 "
        "{%0,%1,%2,%3}, {%4,%5,%6,%7}, {%8,%9}, {%0,%1,%2,%3};"
        : "+f"(c[0]), "+f"(c[1]), "+f"(c[2]), "+f"(c[3])
        : "r"(a[0]), "r"(a[1]), "r"(a[2]), "r"(a[3]), "r"(b[0]), "r"(b[1]));
}

// smem float-index layout (gates kernel):
//   As: 2 stages x [256 rows x 36]        (32 k-floats + pad4)
//   Bs: 3 stages x [32 rows x 136]        (128 n-floats + pad8)
//   Xs: [256 rows x 9]                    (8 i-scales + pad1)
#define ASZ   (256 * 36)
#define BSZ   (32 * 136)
#define BOFF  (2 * ASZ)
#define XOFF  (BOFF + 3 * BSZ)
#define GATES_SMEM_BYTES ((XOFF + 256 * 9) * 4)
// merge kernel: As 3 stages + Bs 3 stages
#define MBOFF (3 * ASZ)
#define MERGE_SMEM_BYTES ((MBOFF + 3 * BSZ) * 4)

// ===========================================================================
// Gates GEMM: C[4096 m, 4096 n], K = 8 i x 4096 j.
// CTA tile 256m x 128n, 512 threads, warps 8(m) x 2(n), warp tile 32m x 64n.
// ===========================================================================
__global__ __launch_bounds__(512) void gates_mma(
    const float* __restrict__ x0, const float* __restrict__ x1,
    const float* __restrict__ h0, const float* __restrict__ h1,
    const float* __restrict__ W1, const float* __restrict__ W2)
{
    extern __shared__ float sm[];
    const uint32_t smb = smem_u32(sm);
    const int tid = threadIdx.x, lane = tid & 31, wid = tid >> 5;
    const int m0 = blockIdx.x * 256;          // m-tile (fast-varying -> W reuse in L2)
    const int n0 = blockIdx.y * 128;
    const float* __restrict__ Wb = (n0 < H_) ? W1 : W2;
    const int nW = n0 & (H_ - 1);

    const int wm = wid & 7, wn = wid >> 3;
    const int lr = lane >> 2, lc = lane & 3;

    // ---- x scales -> smem [256][9]
    for (int idx = tid; idx < 2048; idx += 512) {
        const int row = idx >> 3, i = idx & 7;
        const float v = (i < 4) ? x0[(size_t)(m0 + row) * 4 + i]
                                : x1[(size_t)(m0 + row) * 4 + (i - 4)];
        sm[XOFF + row * 9 + i] = v;
    }

    // ---- cp.async issue lambdas
    auto issue_A = [&](int jb, int buf) {
        const float* hsrc = (jb < 64) ? h0 : h1;
        const int jloc = (jb < 64) ? jb * 32 : jb * 32 - H_;
#pragma unroll
        for (int it = 0; it < 4; it++) {
            const int idx = it * 512 + tid;
            const int row = idx >> 3, c4 = (idx & 7) * 4;
            cpa16(smb + (uint32_t)(buf * ASZ + row * 36 + c4) * 4,
                  hsrc + (size_t)(m0 + row) * H_ + jloc + c4);
        }
    };
    auto issue_B = [&](int jb, int i, int st) {
#pragma unroll
        for (int it = 0; it < 2; it++) {
            const int idx = it * 512 + tid;
            const int row = idx >> 5, c4 = (idx & 31) * 4;
            cpa16(smb + (uint32_t)(BOFF + st * BSZ + row * 136 + c4) * 4,
                  Wb + ((size_t)i * TWOH + jb * 32 + row) * H_ + nW + c4);
        }
    };

    // prologue
    issue_A(0, 0); issue_B(0, 0, 0); CP_COMMIT();
    issue_B(0, 1, 1); CP_COMMIT();

    float acc[2][8][4];
#pragma unroll
    for (int mt = 0; mt < 2; mt++)
#pragma unroll
        for (int nt = 0; nt < 8; nt++)
#pragma unroll
            for (int q = 0; q < 4; q++) acc[mt][nt][q] = 0.f;

    const int brow_base = wn * 64 + lr;            // B frag col within tile

    for (int step = 0; step < 1024; step++) {
        const int jb = step >> 3, i = step & 7, st = step - (step / 3) * 3;
        const int abuf = jb & 1;

        if (step <= 1022) CP_WAIT1(); else CP_WAIT0();
        __syncthreads();

        const float* A = sm + abuf * ASZ;
        const float* Bt = sm + BOFF + st * BSZ;

#pragma unroll
        for (int ks = 0; ks < 4; ks++) {
            // B fragments (shared across mt)
            uint32_t bfr[8][2];
            const int k0 = ks * 8 + lc;
#pragma unroll
            for (int nt = 0; nt < 8; nt++) {
                const int col = brow_base + nt * 8;
                bfr[nt][0] = f2tf(Bt[k0 * 136 + col]);
                bfr[nt][1] = f2tf(Bt[(k0 + 4) * 136 + col]);
            }
#pragma unroll
            for (int mt = 0; mt < 2; mt++) {
                const int r0 = wm * 32 + lr + mt * 16;
                const float xv0 = sm[XOFF + r0 * 9 + i];
                const float xv1 = sm[XOFF + (r0 + 8) * 9 + i];
                uint32_t av[4];
                av[0] = f2tf(A[r0 * 36 + k0] * xv0);
                av[1] = f2tf(A[(r0 + 8) * 36 + k0] * xv1);
                av[2] = f2tf(A[r0 * 36 + k0 + 4] * xv0);
                av[3] = f2tf(A[(r0 + 8) * 36 + k0 + 4] * xv1);
#pragma unroll
                for (int nt = 0; nt < 8; nt++) mma8(acc[mt][nt], av, bfr[nt]);
            }
        }

        const int s2 = step + 2;
        if (s2 <= 1023) {
            const int jb2 = s2 >> 3, i2 = s2 & 7, st2 = s2 - (s2 / 3) * 3;
            issue_B(jb2, i2, st2);
            if (i2 == 0) issue_A(jb2, jb2 & 1);
            CP_COMMIT();
        }
    }

    // writeback
#pragma unroll
    for (int mt = 0; mt < 2; mt++) {
        const int rg = m0 + wm * 32 + lr + mt * 16;
#pragma unroll
        for (int nt = 0; nt < 8; nt++) {
            const int cg = n0 + wn * 64 + nt * 8 + 2 * lc;
            *(float2*)(g_gates + (size_t)rg * TWOH + cg) =
                make_float2(acc[mt][nt][0], acc[mt][nt][1]);
            *(float2*)(g_gates + (size_t)(rg + 8) * TWOH + cg) =
                make_float2(acc[mt][nt][2], acc[mt][nt][3]);
        }
    }
}

// ===========================================================================
// Merge GEMM: C[4096 m, 2048 n] = s @ Wmerge, K = 4096.
// ===========================================================================
__global__ __launch_bounds__(512) void merge_mma(
    const float* __restrict__ h0, const float* __restrict__ h1,
    const float* __restrict__ Wm)
{
    extern __shared__ float sm[];
    const uint32_t smb = smem_u32(sm);
    const int tid = threadIdx.x, lane = tid & 31, wid = tid >> 5;
    const int m0 = blockIdx.x * 256;
    const int n0 = blockIdx.y * 128;
    const int wm = wid & 7, wn = wid >> 3;
    const int lr = lane >> 2, lc = lane & 3;

    auto issue_AB = [&](int jb, int st) {
        const float* hsrc = (jb < 64) ? h0 : h1;
        const int jloc = (jb < 64) ? jb * 32 : jb * 32 - H_;
#pragma unroll
        for (int it = 0; it < 4; it++) {
            const int idx = it * 512 + tid;
            const int row = idx >> 3, c4 = (idx & 7) * 4;
            cpa16(smb + (uint32_t)(st * ASZ + row * 36 + c4) * 4,
                  hsrc + (size_t)(m0 + row) * H_ + jloc + c4);
        }
#pragma unroll
        for (int it = 0; it < 2; it++) {
            const int idx = it * 512 + tid;
            const int row = idx >> 5, c4 = (idx & 31) * 4;
            cpa16(smb + (uint32_t)(MBOFF + st * BSZ + row * 136 + c4) * 4,
                  Wm + (size_t)(jb * 32 + row) * H_ + n0 + c4);
        }
    };

    issue_AB(0, 0); CP_COMMIT();
    issue_AB(1, 1); CP_COMMIT();

    float acc[2][8][4];
#pragma unroll
    for (int mt = 0; mt < 2; mt++)
#pragma unroll
        for (int nt = 0; nt < 8; nt++)
#pragma unroll
            for (int q = 0; q < 4; q++) acc[mt][nt][q] = 0.f;

    const int brow_base = wn * 64 + lr;

    for (int step = 0; step < 128; step++) {
        const int st = step - (step / 3) * 3;

        if (step <= 126) CP_WAIT1(); else CP_WAIT0();
        __syncthreads();

        const float* A = sm + st * ASZ;
        const float* Bt = sm + MBOFF + st * BSZ;

#pragma unroll
        for (int ks = 0; ks < 4; ks++) {
            uint32_t bfr[8][2];
            const int k0 = ks * 8 + lc;
#pragma unroll
            for (int nt = 0; nt < 8; nt++) {
                const int col = brow_base + nt * 8;
                bfr[nt][0] = f2tf(Bt[k0 * 136 + col]);
                bfr[nt][1] = f2tf(Bt[(k0 + 4) * 136 + col]);
            }
#pragma unroll
            for (int mt = 0; mt < 2; mt++) {
                const int r0 = wm * 32 + lr + mt * 16;
                uint32_t av[4];
                av[0] = f2tf(A[r0 * 36 + k0]);
                av[1] = f2tf(A[(r0 + 8) * 36 + k0]);
                av[2] = f2tf(A[r0 * 36 + k0 + 4]);
                av[3] = f2tf(A[(r0 + 8) * 36 + k0 + 4]);
#pragma unroll
                for (int nt = 0; nt < 8; nt++) mma8(acc[mt][nt], av, bfr[nt]);
            }
        }

        const int s2 = step + 2;
        if (s2 <= 127) {
            issue_AB(s2, s2 - (s2 / 3) * 3);
            CP_COMMIT();
        }
    }

#pragma unroll
    for (int mt = 0; mt < 2; mt++) {
        const int rg = m0 + wm * 32 + lr + mt * 16;
#pragma unroll
        for (int nt = 0; nt < 8; nt++) {
            const int cg = n0 + wn * 64 + nt * 8 + 2 * lc;
            *(float2*)(g_merge + (size_t)rg * H_ + cg) =
                make_float2(acc[mt][nt][0], acc[mt][nt][1]);
            *(float2*)(g_merge + (size_t)(rg + 8) * H_ + cg) =
                make_float2(acc[mt][nt][2], acc[mt][nt][3]);
        }
    }
}

// ===========================================================================
// Epilogue
// ===========================================================================
__global__ __launch_bounds__(256) void epilogue_kernel(
    const float* __restrict__ b1, const float* __restrict__ b2,
    float* __restrict__ out)
{
    const size_t idx = (size_t)blockIdx.x * blockDim.x + threadIdx.x;
    const int n = (int)(idx & (H_ - 1));
    const size_t m = idx >> 11;

    const float g1 = g_gates[m * TWOH + n];
    const float g2 = g_gates[m * TWOH + H_ + n];
    const float mv = g_merge[idx];

    const float st = tanhf(g1 + b1[n]);
    const float u  = 1.0f / (1.0f + __expf(-(g2 + b2[n])));
    const float ns = u * st + (1.0f - u) * mv;

    out[idx] = ns;
    out[idx + (size_t)B_ * H_] = ns;
}

// ===========================================================================
extern "C" void kernel_launch(void* const* d_in, const int* in_sizes, int n_in,
                              void* d_out, int out_size)
{
    const float* x0 = (const float*)d_in[0];
    const float* x1 = (const float*)d_in[1];
    const float* h0 = (const float*)d_in[2];
    const float* h1 = (const float*)d_in[3];
    const float* W1 = (const float*)d_in[4];
    const float* b1 = (const float*)d_in[5];
    const float* W2 = (const float*)d_in[6];
    const float* b2 = (const float*)d_in[7];
    const float* Wm = (const float*)d_in[8];
    float* out = (float*)d_out;

    static bool attr_set = false;
    if (!attr_set) {
        cudaFuncSetAttribute(gates_mma, cudaFuncAttributeMaxDynamicSharedMemorySize,
                             GATES_SMEM_BYTES);
        cudaFuncSetAttribute(merge_mma, cudaFuncAttributeMaxDynamicSharedMemorySize,
                             MERGE_SMEM_BYTES);
        attr_set = true;
    }

    gates_mma<<<dim3(16, 32), 512, GATES_SMEM_BYTES>>>(x0, x1, h0, h1, W1, W2);
    merge_mma<<<dim3(16, 16), 512, MERGE_SMEM_BYTES>>>(h0, h1, Wm);

    const size_t total = (size_t)B_ * H_;
    epilogue_kernel<<<(unsigned)(total / 256), 256>>>(b1, b2, out);
}

// round 5
// speedup vs baseline: 5.4271x; 1.7364x over previous
#include <cuda_runtime.h>
#include <cstdint>

#define B_    4096
#define H_    2048
#define TWOH  4096

// scratch
__device__ float g_gates[(size_t)B_ * TWOH];  // [B, 4096] : g1 | g2
__device__ float g_merge[(size_t)B_ * H_];    // [B, 2048]

// ---------------- helpers ----------------
__device__ __forceinline__ uint32_t smem_u32(const void* p) {
    uint32_t a;
    asm("{ .reg .u64 t; cvta.to.shared.u64 t, %1; cvt.u32.u64 %0, t; }" : "=r"(a) : "l"(p));
    return a;
}
__device__ __forceinline__ void cpa16(uint32_t dst, const void* src) {
    asm volatile("cp.async.cg.shared.global [%0], [%1], 16;" :: "r"(dst), "l"(src));
}
#define CP_COMMIT() asm volatile("cp.async.commit_group;")
#define CP_WAIT2()  asm volatile("cp.async.wait_group 2;")
#define CP_WAIT1()  asm volatile("cp.async.wait_group 1;")
#define CP_WAIT0()  asm volatile("cp.async.wait_group 0;")

// pack two fp32 -> half2 (lo = second operand)
__device__ __forceinline__ uint32_t pk2h(float hi, float lo) {
    uint32_t d; asm("cvt.rn.f16x2.f32 %0, %1, %2;" : "=r"(d) : "f"(hi), "f"(lo)); return d;
}
__device__ __forceinline__ uint32_t hmul2(uint32_t a, uint32_t b) {
    uint32_t d; asm("mul.rn.f16x2 %0, %1, %2;" : "=r"(d) : "r"(a), "r"(b)); return d;
}
__device__ __forceinline__ void ldsm4t(uint32_t& r0, uint32_t& r1, uint32_t& r2, uint32_t& r3,
                                       uint32_t addr) {
    asm volatile("ldmatrix.sync.aligned.m8n8.x4.trans.shared.b16 {%0,%1,%2,%3}, [%4];"
                 : "=r"(r0), "=r"(r1), "=r"(r2), "=r"(r3) : "r"(addr));
}
__device__ __forceinline__ void mma16(float* c, const uint32_t* a, const uint32_t* b) {
    asm volatile(
        "mma.sync.aligned.m16n8k16.row.col.f32.f16.f16.f32 "
        "{%0,%1,%2,%3}, {%4,%5,%6,%7}, {%8,%9}, {%0,%1,%2,%3};"
        : "+f"(c[0]), "+f"(c[1]), "+f"(c[2]), "+f"(c[3])
        : "r"(a[0]), "r"(a[1]), "r"(a[2]), "r"(a[3]), "r"(b[0]), "r"(b[1]));
}

// ---------------- smem layout constants (word = 4B) ----------------
#define PA    36            // s_raw row stride (fp32)
#define PBR   136           // B_raw row stride (fp32)
#define PBH   136           // B_half row stride (halfs); 68 words
#define SRAW_W  (256 * PA)  // 9216 words per stage
#define BRAW_W  (32 * PBR)  // 4352 words per stage
#define BHALF_W (32 * 68)   // 2176 words per stage

// gates: sraw x2 | braw x3 | bhalf x3 | xd (512 x 33 words)
#define G_BRAW   (2 * SRAW_W)                 // 18432
#define G_BHALF  (G_BRAW + 3 * BRAW_W)        // 31488
#define G_XD     (G_BHALF + 3 * BHALF_W)      // 38016
#define G_WORDS  (G_XD + 512 * 33)            // 54912 -> 219648 B
// merge: sraw x3 | braw x3 | bhalf x3
#define M_BRAW   (3 * SRAW_W)                 // 27648
#define M_BHALF  (M_BRAW + 3 * BRAW_W)        // 40704
#define M_WORDS  (M_BHALF + 3 * BHALF_W)      // 47232 -> 188928 B

// ===========================================================================
// Gates GEMM: C[4096 m, 4096 n], K = 8 i x 4096 j, fp16 MMA.
// CTA 256m x 128n, 512 thr, warps 8(m) x 2(n), warp tile 32m x 64n.
// ===========================================================================
__global__ __launch_bounds__(512) void gates_mma(
    const float* __restrict__ x0, const float* __restrict__ x1,
    const float* __restrict__ h0, const float* __restrict__ h1,
    const float* __restrict__ W1, const float* __restrict__ W2)
{
    extern __shared__ float sm[];
    uint32_t* usm = (uint32_t*)sm;
    const uint32_t smb = smem_u32(sm);
    const int tid = threadIdx.x, lane = tid & 31, wid = tid >> 5;
    const int m0 = blockIdx.x * 256;
    const int n0 = blockIdx.y * 128;
    const float* __restrict__ Wb = (n0 < H_) ? W1 : W2;
    const int nW = n0 & (H_ - 1);
    const int wm = wid & 7, wn = wid >> 3;
    const int lr = lane >> 2, lc = lane & 3;

    // ---- xd preload: duplicated-half2 x-scales, [tid][r*8+i], padded stride 33
    {
#pragma unroll
        for (int r = 0; r < 4; r++) {
            const int rowg = m0 + wm * 32 + (r >> 1) * 16 + (r & 1) * 8 + lr;
            const float4 a = *(const float4*)(x0 + (size_t)rowg * 4);
            const float4 b = *(const float4*)(x1 + (size_t)rowg * 4);
            const float xv[8] = {a.x, a.y, a.z, a.w, b.x, b.y, b.z, b.w};
#pragma unroll
            for (int i = 0; i < 8; i++)
                usm[G_XD + tid * 33 + r * 8 + i] = pk2h(xv[i], xv[i]);
        }
    }

    auto issue_B = [&](int s3) {
        const int jb = s3 >> 3, i = s3 & 7, st = s3 % 3;
#pragma unroll
        for (int it = 0; it < 2; it++) {
            const int idx = it * 512 + tid, row = idx >> 5, c4 = (idx & 31) * 4;
            cpa16(smb + (uint32_t)(G_BRAW + st * BRAW_W + row * PBR + c4) * 4,
                  Wb + ((size_t)i * TWOH + jb * 32 + row) * H_ + nW + c4);
        }
    };
    auto issue_S = [&](int jb) {
        const float* hsrc = (jb < 64) ? h0 : h1;
        const int jloc = (jb < 64) ? jb * 32 : jb * 32 - H_;
#pragma unroll
        for (int it = 0; it < 4; it++) {
            const int idx = it * 512 + tid, row = idx >> 3, c4 = (idx & 7) * 4;
            cpa16(smb + (uint32_t)((jb & 1) * SRAW_W + row * PA + c4) * 4,
                  hsrc + (size_t)(m0 + row) * H_ + jloc + c4);
        }
    };
    auto convert_B = [&](int st) {   // raw stage st -> half stage st (self-visible data)
        const float* src = sm + G_BRAW + st * BRAW_W;
        uint32_t* dst = usm + G_BHALF + st * BHALF_W;
#pragma unroll
        for (int it = 0; it < 2; it++) {
            const int idx = it * 512 + tid, row = idx >> 5, c = idx & 31;
            float4 v = *(const float4*)(src + row * PBR + c * 4);
            uint2 hh; hh.x = pk2h(v.y, v.x); hh.y = pk2h(v.w, v.z);
            *(uint2*)(dst + row * 68 + c * 2) = hh;
        }
    };

    // ---- prologue
    issue_B(0); issue_S(0); CP_COMMIT();
    issue_B(1); CP_COMMIT();
    issue_B(2); CP_COMMIT();
    CP_WAIT2();
    __syncthreads();
    convert_B(0);

    float acc[2][8][4];
#pragma unroll
    for (int mt = 0; mt < 2; mt++)
#pragma unroll
        for (int nt = 0; nt < 8; nt++)
#pragma unroll
            for (int q = 0; q < 4; q++) acc[mt][nt][q] = 0.f;

    uint32_t sreg[16];
    const uint32_t lm_half = (uint32_t)((lane & 15) * PBH + wn * 64 + ((lane >> 4) << 3));
    int stA = 0, st1 = 1;   // s%3, (s+1)%3

    for (int s = 0; s < 1024; s++) {
        const int jb = s >> 3, i = s & 7;

        if (s >= 1022) { CP_WAIT0(); } else { CP_WAIT1(); }

        if (i == 0) {
            // convert s -> half regs (unscaled), reused for 8 i-steps
            const float* sp = sm + (jb & 1) * SRAW_W;
#pragma unroll
            for (int mt = 0; mt < 2; mt++)
#pragma unroll
                for (int ks = 0; ks < 2; ks++) {
                    const int base = (wm * 32 + mt * 16 + lr) * PA + ks * 16 + 2 * lc;
                    float2 v0 = *(const float2*)(sp + base);
                    float2 v1 = *(const float2*)(sp + base + 8 * PA);
                    float2 v2 = *(const float2*)(sp + base + 8);
                    float2 v3 = *(const float2*)(sp + base + 8 * PA + 8);
                    sreg[mt * 8 + ks * 4 + 0] = pk2h(v0.y, v0.x);
                    sreg[mt * 8 + ks * 4 + 1] = pk2h(v1.y, v1.x);
                    sreg[mt * 8 + ks * 4 + 2] = pk2h(v2.y, v2.x);
                    sreg[mt * 8 + ks * 4 + 3] = pk2h(v3.y, v3.x);
                }
        }
        if (s + 1 <= 1023) convert_B(st1);
        __syncthreads();

        // x-scale half2 (duplicated) for this i, 4 rows
        uint32_t xd[4];
#pragma unroll
        for (int r = 0; r < 4; r++) xd[r] = usm[G_XD + tid * 33 + r * 8 + i];

        const uint32_t bh_byte = smb + (uint32_t)(G_BHALF + stA * BHALF_W) * 4;
#pragma unroll
        for (int ks = 0; ks < 2; ks++) {
            uint32_t bfr[8][2];
#pragma unroll
            for (int p = 0; p < 4; p++) {
                uint32_t addr = bh_byte + (uint32_t)(ks * 16 * PBH) * 2 + lm_half * 2 + p * 32;
                uint32_t r0, r1, r2, r3;
                ldsm4t(r0, r1, r2, r3, addr);
                bfr[2 * p][0] = r0; bfr[2 * p][1] = r1;
                bfr[2 * p + 1][0] = r2; bfr[2 * p + 1][1] = r3;
            }
#pragma unroll
            for (int mt = 0; mt < 2; mt++) {
                uint32_t a[4];
                a[0] = hmul2(sreg[mt * 8 + ks * 4 + 0], xd[mt * 2]);
                a[1] = hmul2(sreg[mt * 8 + ks * 4 + 1], xd[mt * 2 + 1]);
                a[2] = hmul2(sreg[mt * 8 + ks * 4 + 2], xd[mt * 2]);
                a[3] = hmul2(sreg[mt * 8 + ks * 4 + 3], xd[mt * 2 + 1]);
#pragma unroll
                for (int nt = 0; nt < 8; nt++) mma16(acc[mt][nt], a, bfr[nt]);
            }
        }

        if (s + 3 <= 1023) {
            issue_B(s + 3);
            if ((s & 7) == 2 && jb + 1 <= 127) issue_S(jb + 1);
            CP_COMMIT();
        }
        stA = st1; st1 = (st1 == 2) ? 0 : st1 + 1;
    }

    // ---- writeback
#pragma unroll
    for (int mt = 0; mt < 2; mt++) {
        const int rg = m0 + wm * 32 + lr + mt * 16;
#pragma unroll
        for (int nt = 0; nt < 8; nt++) {
            const int cg = n0 + wn * 64 + nt * 8 + 2 * lc;
            *(float2*)(g_gates + (size_t)rg * TWOH + cg) =
                make_float2(acc[mt][nt][0], acc[mt][nt][1]);
            *(float2*)(g_gates + (size_t)(rg + 8) * TWOH + cg) =
                make_float2(acc[mt][nt][2], acc[mt][nt][3]);
        }
    }
}

// ===========================================================================
// Merge GEMM: C[4096 m, 2048 n] = s @ Wmerge, K = 4096, fp16 MMA.
// ===========================================================================
__global__ __launch_bounds__(512) void merge_mma(
    const float* __restrict__ h0, const float* __restrict__ h1,
    const float* __restrict__ Wm)
{
    extern __shared__ float sm[];
    uint32_t* usm = (uint32_t*)sm;
    const uint32_t smb = smem_u32(sm);
    const int tid = threadIdx.x, lane = tid & 31, wid = tid >> 5;
    const int m0 = blockIdx.x * 256;
    const int n0 = blockIdx.y * 128;
    const int wm = wid & 7, wn = wid >> 3;
    const int lr = lane >> 2, lc = lane & 3;

    auto issue_B = [&](int s2) {
        const int st = s2 % 3;
#pragma unroll
        for (int it = 0; it < 2; it++) {
            const int idx = it * 512 + tid, row = idx >> 5, c4 = (idx & 31) * 4;
            cpa16(smb + (uint32_t)(M_BRAW + st * BRAW_W + row * PBR + c4) * 4,
                  Wm + (size_t)(s2 * 32 + row) * H_ + n0 + c4);
        }
    };
    auto issue_S = [&](int s2) {
        const int st = s2 % 3;
        const float* hsrc = (s2 < 64) ? h0 : h1;
        const int jloc = (s2 < 64) ? s2 * 32 : s2 * 32 - H_;
#pragma unroll
        for (int it = 0; it < 4; it++) {
            const int idx = it * 512 + tid, row = idx >> 3, c4 = (idx & 7) * 4;
            cpa16(smb + (uint32_t)(st * SRAW_W + row * PA + c4) * 4,
                  hsrc + (size_t)(m0 + row) * H_ + jloc + c4);
        }
    };
    auto convert_B = [&](int st) {
        const float* src = sm + M_BRAW + st * BRAW_W;
        uint32_t* dst = usm + M_BHALF + st * BHALF_W;
#pragma unroll
        for (int it = 0; it < 2; it++) {
            const int idx = it * 512 + tid, row = idx >> 5, c = idx & 31;
            float4 v = *(const float4*)(src + row * PBR + c * 4);
            uint2 hh; hh.x = pk2h(v.y, v.x); hh.y = pk2h(v.w, v.z);
            *(uint2*)(dst + row * 68 + c * 2) = hh;
        }
    };

    issue_B(0); issue_S(0); CP_COMMIT();
    issue_B(1); issue_S(1); CP_COMMIT();
    CP_WAIT1();
    __syncthreads();
    convert_B(0);

    float acc[2][8][4];
#pragma unroll
    for (int mt = 0; mt < 2; mt++)
#pragma unroll
        for (int nt = 0; nt < 8; nt++)
#pragma unroll
            for (int q = 0; q < 4; q++) acc[mt][nt][q] = 0.f;

    const uint32_t lm_half = (uint32_t)((lane & 15) * PBH + wn * 64 + ((lane >> 4) << 3));
    int stA = 0, st1 = 1;

    for (int s = 0; s < 128; s++) {
        CP_WAIT0();
        if (s + 1 <= 127) convert_B(st1);
        __syncthreads();

        // s -> half regs for this step
        uint32_t sreg[16];
        {
            const float* sp = sm + stA * SRAW_W;
#pragma unroll
            for (int mt = 0; mt < 2; mt++)
#pragma unroll
                for (int ks = 0; ks < 2; ks++) {
                    const int base = (wm * 32 + mt * 16 + lr) * PA + ks * 16 + 2 * lc;
                    float2 v0 = *(const float2*)(sp + base);
                    float2 v1 = *(const float2*)(sp + base + 8 * PA);
                    float2 v2 = *(const float2*)(sp + base + 8);
                    float2 v3 = *(const float2*)(sp + base + 8 * PA + 8);
                    sreg[mt * 8 + ks * 4 + 0] = pk2h(v0.y, v0.x);
                    sreg[mt * 8 + ks * 4 + 1] = pk2h(v1.y, v1.x);
                    sreg[mt * 8 + ks * 4 + 2] = pk2h(v2.y, v2.x);
                    sreg[mt * 8 + ks * 4 + 3] = pk2h(v3.y, v3.x);
                }
        }

        const uint32_t bh_byte = smb + (uint32_t)(M_BHALF + stA * BHALF_W) * 4;
#pragma unroll
        for (int ks = 0; ks < 2; ks++) {
            uint32_t bfr[8][2];
#pragma unroll
            for (int p = 0; p < 4; p++) {
                uint32_t addr = bh_byte + (uint32_t)(ks * 16 * PBH) * 2 + lm_half * 2 + p * 32;
                uint32_t r0, r1, r2, r3;
                ldsm4t(r0, r1, r2, r3, addr);
                bfr[2 * p][0] = r0; bfr[2 * p][1] = r1;
                bfr[2 * p + 1][0] = r2; bfr[2 * p + 1][1] = r3;
            }
#pragma unroll
            for (int mt = 0; mt < 2; mt++) {
#pragma unroll
                for (int nt = 0; nt < 8; nt++)
                    mma16(acc[mt][nt], &sreg[mt * 8 + ks * 4], bfr[nt]);
            }
        }

        if (s + 2 <= 127) { issue_B(s + 2); issue_S(s + 2); CP_COMMIT(); }
        stA = st1; st1 = (st1 == 2) ? 0 : st1 + 1;
    }

#pragma unroll
    for (int mt = 0; mt < 2; mt++) {
        const int rg = m0 + wm * 32 + lr + mt * 16;
#pragma unroll
        for (int nt = 0; nt < 8; nt++) {
            const int cg = n0 + wn * 64 + nt * 8 + 2 * lc;
            *(float2*)(g_merge + (size_t)rg * H_ + cg) =
                make_float2(acc[mt][nt][0], acc[mt][nt][1]);
            *(float2*)(g_merge + (size_t)(rg + 8) * H_ + cg) =
                make_float2(acc[mt][nt][2], acc[mt][nt][3]);
        }
    }
}

// ===========================================================================
// Epilogue
// ===========================================================================
__global__ __launch_bounds__(256) void epilogue_kernel(
    const float* __restrict__ b1, const float* __restrict__ b2,
    float* __restrict__ out)
{
    const size_t idx = (size_t)blockIdx.x * blockDim.x + threadIdx.x;
    const int n = (int)(idx & (H_ - 1));
    const size_t m = idx >> 11;

    const float g1 = g_gates[m * TWOH + n];
    const float g2 = g_gates[m * TWOH + H_ + n];
    const float mv = g_merge[idx];

    const float st = tanhf(g1 + b1[n]);
    const float u  = 1.0f / (1.0f + __expf(-(g2 + b2[n])));
    const float ns = u * st + (1.0f - u) * mv;

    out[idx] = ns;
    out[idx + (size_t)B_ * H_] = ns;
}

// ===========================================================================
extern "C" void kernel_launch(void* const* d_in, const int* in_sizes, int n_in,
                              void* d_out, int out_size)
{
    const float* x0 = (const float*)d_in[0];
    const float* x1 = (const float*)d_in[1];
    const float* h0 = (const float*)d_in[2];
    const float* h1 = (const float*)d_in[3];
    const float* W1 = (const float*)d_in[4];
    const float* b1 = (const float*)d_in[5];
    const float* W2 = (const float*)d_in[6];
    const float* b2 = (const float*)d_in[7];
    const float* Wm = (const float*)d_in[8];
    float* out = (float*)d_out;

    static bool attr_set = false;
    if (!attr_set) {
        cudaFuncSetAttribute(gates_mma, cudaFuncAttributeMaxDynamicSharedMemorySize,
                             G_WORDS * 4);
        cudaFuncSetAttribute(merge_mma, cudaFuncAttributeMaxDynamicSharedMemorySize,
                             M_WORDS * 4);
        attr_set = true;
    }

    gates_mma<<<dim3(16, 32), 512, G_WORDS * 4>>>(x0, x1, h0, h1, W1, W2);
    merge_mma<<<dim3(16, 16), 512, M_WORDS * 4>>>(h0, h1, Wm);

    const size_t total = (size_t)B_ * H_;
    epilogue_kernel<<<(unsigned)(total / 256), 256>>>(b1, b2, out);
}

// round 6
// speedup vs baseline: 6.0107x; 1.1075x over previous
#include <cuda_runtime.h>
#include <cuda_fp16.h>
#include <cstdint>

#define B_    4096
#define H_    2048
#define TWOH  4096

// ---------------- device scratch ----------------
__device__ __half g_Wh[(size_t)8 * TWOH * TWOH];   // [8][4096 j][4096 n] (W1 | W2 on n)
__device__ __half g_Wmh[(size_t)TWOH * H_];        // [4096 j][2048 n]
__device__ __half g_sh[(size_t)B_ * TWOH];         // [4096 m][4096 j]  (h0 | h1 on j)
__device__ float  g_gates[(size_t)B_ * TWOH];      // [B][4096] g1 | g2
__device__ float  g_merge[(size_t)B_ * H_];

// ---------------- helpers ----------------
__device__ __forceinline__ uint32_t smem_u32(const void* p) {
    uint32_t a;
    asm("{ .reg .u64 t; cvta.to.shared.u64 t, %1; cvt.u32.u64 %0, t; }" : "=r"(a) : "l"(p));
    return a;
}
__device__ __forceinline__ void cpa16(uint32_t dst, const void* src) {
    asm volatile("cp.async.cg.shared.global [%0], [%1], 16;" :: "r"(dst), "l"(src));
}
#define CP_COMMIT() asm volatile("cp.async.commit_group;")
#define CP_WAIT2()  asm volatile("cp.async.wait_group 2;")
#define CP_WAIT0()  asm volatile("cp.async.wait_group 0;")

__device__ __forceinline__ uint32_t pk2h(float hi, float lo) {
    uint32_t d; asm("cvt.rn.f16x2.f32 %0, %1, %2;" : "=r"(d) : "f"(hi), "f"(lo)); return d;
}
__device__ __forceinline__ uint32_t hmul2(uint32_t a, uint32_t b) {
    uint32_t d; asm("mul.rn.f16x2 %0, %1, %2;" : "=r"(d) : "r"(a), "r"(b)); return d;
}
__device__ __forceinline__ void ldsm4(uint32_t& r0, uint32_t& r1, uint32_t& r2, uint32_t& r3,
                                      uint32_t addr) {
    asm volatile("ldmatrix.sync.aligned.m8n8.x4.shared.b16 {%0,%1,%2,%3}, [%4];"
                 : "=r"(r0), "=r"(r1), "=r"(r2), "=r"(r3) : "r"(addr));
}
__device__ __forceinline__ void ldsm4t(uint32_t& r0, uint32_t& r1, uint32_t& r2, uint32_t& r3,
                                       uint32_t addr) {
    asm volatile("ldmatrix.sync.aligned.m8n8.x4.trans.shared.b16 {%0,%1,%2,%3}, [%4];"
                 : "=r"(r0), "=r"(r1), "=r"(r2), "=r"(r3) : "r"(addr));
}
__device__ __forceinline__ void mma16(float* c, const uint32_t* a, const uint32_t* b) {
    asm volatile(
        "mma.sync.aligned.m16n8k16.row.col.f32.f16.f16.f32 "
        "{%0,%1,%2,%3}, {%4,%5,%6,%7}, {%8,%9}, {%0,%1,%2,%3};"
        : "+f"(c[0]), "+f"(c[1]), "+f"(c[2]), "+f"(c[3])
        : "r"(a[0]), "r"(a[1]), "r"(a[2]), "r"(a[3]), "r"(b[0]), "r"(b[1]));
}

// ---------------- pack kernels (fp32 -> fp16, fused concat) ----------------
__global__ __launch_bounds__(256) void pack_W(const float* __restrict__ W1,
                                              const float* __restrict__ W2,
                                              __half* __restrict__ dst) {
    const size_t idx = ((size_t)blockIdx.x * 256 + threadIdx.x) * 8;
    const int ng = (int)(idx & (TWOH - 1));
    const size_t ij = idx >> 12;
    const float* src = (ng < H_) ? (W1 + ij * H_ + ng) : (W2 + ij * H_ + (ng - H_));
    const float4 v0 = *(const float4*)src;
    const float4 v1 = *(const float4*)(src + 4);
    uint4 o;
    o.x = pk2h(v0.y, v0.x); o.y = pk2h(v0.w, v0.z);
    o.z = pk2h(v1.y, v1.x); o.w = pk2h(v1.w, v1.z);
    *(uint4*)(dst + idx) = o;
}
__global__ __launch_bounds__(256) void pack_s(const float* __restrict__ h0,
                                              const float* __restrict__ h1,
                                              __half* __restrict__ dst) {
    const size_t idx = ((size_t)blockIdx.x * 256 + threadIdx.x) * 8;
    const int j = (int)(idx & (TWOH - 1));
    const size_t m = idx >> 12;
    const float* src = (j < H_) ? (h0 + m * H_ + j) : (h1 + m * H_ + (j - H_));
    const float4 v0 = *(const float4*)src;
    const float4 v1 = *(const float4*)(src + 4);
    uint4 o;
    o.x = pk2h(v0.y, v0.x); o.y = pk2h(v0.w, v0.z);
    o.z = pk2h(v1.y, v1.x); o.w = pk2h(v1.w, v1.z);
    *(uint4*)(dst + idx) = o;
}
__global__ __launch_bounds__(256) void pack_Wm(const float* __restrict__ src,
                                               __half* __restrict__ dst) {
    const size_t idx = ((size_t)blockIdx.x * 256 + threadIdx.x) * 8;
    const float4 v0 = *(const float4*)(src + idx);
    const float4 v1 = *(const float4*)(src + idx + 4);
    uint4 o;
    o.x = pk2h(v0.y, v0.x); o.y = pk2h(v0.w, v0.z);
    o.z = pk2h(v1.y, v1.x); o.w = pk2h(v1.w, v1.z);
    *(uint4*)(dst + idx) = o;
}

// ---------------- smem layout (halfs / bytes) ----------------
// gates: A 2 stages x [128 rows x 40 halfs] ; B 4 stages x [32 k x 136 halfs] ; xd [128x9] words
#define GA_ROW    40
#define GA_STG    (128 * GA_ROW)       // 5120 halfs
#define GB_ROW    136
#define GB_STG    (32 * GB_ROW)        // 4352 halfs
#define GB_OFF_B  (2 * GA_STG * 2)     // 20480 bytes
#define GXD_OFF_W ((GB_OFF_B + 4 * GB_STG * 2) / 4)  // word index 13824
#define G_SMEM_B  (GB_OFF_B + 4 * GB_STG * 2 + 128 * 9 * 4)  // 59904
// merge: A 4 stages + B 4 stages
#define MB_OFF_B  (4 * GA_STG * 2)     // 40960 bytes
#define M_SMEM_B  (MB_OFF_B + 4 * GB_STG * 2)  // 75776

// ===========================================================================
// Gates GEMM: C[4096,4096] fp16 MMA, CTA 128m x 128n, 256 thr, 2 CTA/SM.
// ===========================================================================
__global__ __launch_bounds__(256, 2) void gates_mma(
    const __half* __restrict__ Wh, const __half* __restrict__ sh,
    const float* __restrict__ x0, const float* __restrict__ x1)
{
    extern __shared__ __align__(16) char smc[];
    uint32_t* usm = (uint32_t*)smc;
    const uint32_t smb = smem_u32(smc);
    const int tid = threadIdx.x, lane = tid & 31, wid = tid >> 5;
    const int m0 = blockIdx.x * 128;   // m fastest -> W dedup in L2
    const int n0 = blockIdx.y * 128;
    const int wm = wid & 3, wn = wid >> 2;
    const int lr = lane >> 2, lc = lane & 3;

    // xd: duplicated half2 x-scales [128 rows][8 i], padded stride 9 words
    for (int idx = tid; idx < 1024; idx += 256) {
        const int row = idx >> 3, i = idx & 7;
        const float v = (i < 4) ? x0[(size_t)(m0 + row) * 4 + i]
                                : x1[(size_t)(m0 + row) * 4 + (i - 4)];
        usm[GXD_OFF_W + row * 9 + i] = pk2h(v, v);
    }

    auto issue_B = [&](int s) {
        const int jb = s >> 3, i = s & 7, st = s & 3;
#pragma unroll
        for (int it = 0; it < 2; it++) {
            const int idx = it * 256 + tid, row = idx >> 4, c = idx & 15;
            cpa16(smb + GB_OFF_B + (uint32_t)(st * GB_STG + row * GB_ROW + c * 8) * 2,
                  Wh + ((size_t)i * TWOH + jb * 32 + row) * TWOH + n0 + c * 8);
        }
    };
    auto issue_A = [&](int jb) {
#pragma unroll
        for (int it = 0; it < 2; it++) {
            const int idx = it * 256 + tid, row = idx >> 2, c = idx & 3;
            cpa16(smb + (uint32_t)(((jb & 1) * 128 + row) * GA_ROW + c * 8) * 2,
                  sh + (size_t)(m0 + row) * TWOH + jb * 32 + c * 8);
        }
    };

    // prologue: 3 groups
    issue_A(0); issue_B(0); CP_COMMIT();
    issue_B(1); CP_COMMIT();
    issue_B(2); CP_COMMIT();

    float acc[2][8][4];
#pragma unroll
    for (int mt = 0; mt < 2; mt++)
#pragma unroll
        for (int nt = 0; nt < 8; nt++)
#pragma unroll
            for (int q = 0; q < 4; q++) acc[mt][nt][q] = 0.f;

    uint32_t areg[2][2][4];   // [mt][ks][frag], reused across 8 i-steps
    const uint32_t a_lane_off = (uint32_t)(lane & 15) * (GA_ROW * 2) +
                                ((lane >> 4) & 1) * 16;
    const uint32_t b_lane_off = (uint32_t)(lane & 15) * (GB_ROW * 2) +
                                (uint32_t)(wn * 64 + ((lane >> 4) << 3)) * 2;

    for (int s = 0; s < 1024; s++) {
        const int jb = s >> 3, i = s & 7;

        if (s >= 1021) { CP_WAIT0(); } else { CP_WAIT2(); }
        __syncthreads();

        if (i == 0) {
            const uint32_t ab = smb + (uint32_t)((jb & 1) * 128 + wm * 32) * (GA_ROW * 2);
#pragma unroll
            for (int mt = 0; mt < 2; mt++)
#pragma unroll
                for (int ks = 0; ks < 2; ks++)
                    ldsm4(areg[mt][ks][0], areg[mt][ks][1], areg[mt][ks][2], areg[mt][ks][3],
                          ab + (uint32_t)mt * 16 * (GA_ROW * 2) + a_lane_off + ks * 32);
        }

        uint32_t xd[4];
#pragma unroll
        for (int mt = 0; mt < 2; mt++) {
            xd[mt * 2]     = usm[GXD_OFF_W + (wm * 32 + mt * 16 + lr) * 9 + i];
            xd[mt * 2 + 1] = usm[GXD_OFF_W + (wm * 32 + mt * 16 + 8 + lr) * 9 + i];
        }

        const uint32_t bb = smb + GB_OFF_B + (uint32_t)(s & 3) * (GB_STG * 2);
#pragma unroll
        for (int ks = 0; ks < 2; ks++) {
            uint32_t bfr[8][2];
#pragma unroll
            for (int p = 0; p < 4; p++) {
                uint32_t r0, r1, r2, r3;
                ldsm4t(r0, r1, r2, r3,
                       bb + (uint32_t)ks * 16 * (GB_ROW * 2) + b_lane_off + p * 32);
                bfr[2 * p][0] = r0; bfr[2 * p][1] = r1;
                bfr[2 * p + 1][0] = r2; bfr[2 * p + 1][1] = r3;
            }
#pragma unroll
            for (int mt = 0; mt < 2; mt++) {
                uint32_t a[4];
                a[0] = hmul2(areg[mt][ks][0], xd[2 * mt]);
                a[1] = hmul2(areg[mt][ks][1], xd[2 * mt + 1]);
                a[2] = hmul2(areg[mt][ks][2], xd[2 * mt]);
                a[3] = hmul2(areg[mt][ks][3], xd[2 * mt + 1]);
#pragma unroll
                for (int nt = 0; nt < 8; nt++) mma16(acc[mt][nt], a, bfr[nt]);
            }
        }

        if (s + 3 < 1024) {
            issue_B(s + 3);
            if (i == 4 && jb + 1 < 128) issue_A(jb + 1);
            CP_COMMIT();
        }
    }

#pragma unroll
    for (int mt = 0; mt < 2; mt++) {
        const int rg = m0 + wm * 32 + mt * 16 + lr;
#pragma unroll
        for (int nt = 0; nt < 8; nt++) {
            const int cg = n0 + wn * 64 + nt * 8 + 2 * lc;
            *(float2*)(g_gates + (size_t)rg * TWOH + cg) =
                make_float2(acc[mt][nt][0], acc[mt][nt][1]);
            *(float2*)(g_gates + (size_t)(rg + 8) * TWOH + cg) =
                make_float2(acc[mt][nt][2], acc[mt][nt][3]);
        }
    }
}

// ===========================================================================
// Merge GEMM: C[4096,2048] = s @ Wmerge, fp16 MMA, CTA 128x128.
// ===========================================================================
__global__ __launch_bounds__(256, 2) void merge_mma(
    const __half* __restrict__ Wmh, const __half* __restrict__ sh)
{
    extern __shared__ __align__(16) char smc[];
    const uint32_t smb = smem_u32(smc);
    const int tid = threadIdx.x, lane = tid & 31, wid = tid >> 5;
    const int m0 = blockIdx.x * 128;
    const int n0 = blockIdx.y * 128;
    const int wm = wid & 3, wn = wid >> 2;
    const int lr = lane >> 2, lc = lane & 3;

    auto issue_AB = [&](int s) {
        const int st = s & 3;
#pragma unroll
        for (int it = 0; it < 2; it++) {
            const int idx = it * 256 + tid, row = idx >> 2, c = idx & 3;
            cpa16(smb + (uint32_t)((st * 128 + row) * GA_ROW + c * 8) * 2,
                  sh + (size_t)(m0 + row) * TWOH + s * 32 + c * 8);
        }
#pragma unroll
        for (int it = 0; it < 2; it++) {
            const int idx = it * 256 + tid, row = idx >> 4, c = idx & 15;
            cpa16(smb + MB_OFF_B + (uint32_t)(st * GB_STG + row * GB_ROW + c * 8) * 2,
                  Wmh + (size_t)(s * 32 + row) * H_ + n0 + c * 8);
        }
    };

    issue_AB(0); CP_COMMIT();
    issue_AB(1); CP_COMMIT();
    issue_AB(2); CP_COMMIT();

    float acc[2][8][4];
#pragma unroll
    for (int mt = 0; mt < 2; mt++)
#pragma unroll
        for (int nt = 0; nt < 8; nt++)
#pragma unroll
            for (int q = 0; q < 4; q++) acc[mt][nt][q] = 0.f;

    const uint32_t a_lane_off = (uint32_t)(lane & 15) * (GA_ROW * 2) +
                                ((lane >> 4) & 1) * 16;
    const uint32_t b_lane_off = (uint32_t)(lane & 15) * (GB_ROW * 2) +
                                (uint32_t)(wn * 64 + ((lane >> 4) << 3)) * 2;

    for (int s = 0; s < 128; s++) {
        if (s >= 125) { CP_WAIT0(); } else { CP_WAIT2(); }
        __syncthreads();

        uint32_t areg[2][2][4];
        const uint32_t ab = smb + (uint32_t)((s & 3) * 128 + wm * 32) * (GA_ROW * 2);
#pragma unroll
        for (int mt = 0; mt < 2; mt++)
#pragma unroll
            for (int ks = 0; ks < 2; ks++)
                ldsm4(areg[mt][ks][0], areg[mt][ks][1], areg[mt][ks][2], areg[mt][ks][3],
                      ab + (uint32_t)mt * 16 * (GA_ROW * 2) + a_lane_off + ks * 32);

        const uint32_t bb = smb + MB_OFF_B + (uint32_t)(s & 3) * (GB_STG * 2);
#pragma unroll
        for (int ks = 0; ks < 2; ks++) {
            uint32_t bfr[8][2];
#pragma unroll
            for (int p = 0; p < 4; p++) {
                uint32_t r0, r1, r2, r3;
                ldsm4t(r0, r1, r2, r3,
                       bb + (uint32_t)ks * 16 * (GB_ROW * 2) + b_lane_off + p * 32);
                bfr[2 * p][0] = r0; bfr[2 * p][1] = r1;
                bfr[2 * p + 1][0] = r2; bfr[2 * p + 1][1] = r3;
            }
#pragma unroll
            for (int mt = 0; mt < 2; mt++)
#pragma unroll
                for (int nt = 0; nt < 8; nt++)
                    mma16(acc[mt][nt], areg[mt][ks], bfr[nt]);
        }

        if (s + 3 < 128) { issue_AB(s + 3); CP_COMMIT(); }
    }

#pragma unroll
    for (int mt = 0; mt < 2; mt++) {
        const int rg = m0 + wm * 32 + mt * 16 + lr;
#pragma unroll
        for (int nt = 0; nt < 8; nt++) {
            const int cg = n0 + wn * 64 + nt * 8 + 2 * lc;
            *(float2*)(g_merge + (size_t)rg * H_ + cg) =
                make_float2(acc[mt][nt][0], acc[mt][nt][1]);
            *(float2*)(g_merge + (size_t)(rg + 8) * H_ + cg) =
                make_float2(acc[mt][nt][2], acc[mt][nt][3]);
        }
    }
}

// ===========================================================================
// Epilogue (vectorized)
// ===========================================================================
__global__ __launch_bounds__(256) void epilogue_kernel(
    const float* __restrict__ b1, const float* __restrict__ b2,
    float* __restrict__ out)
{
    const size_t idx = ((size_t)blockIdx.x * 256 + threadIdx.x) * 4;
    const int n = (int)(idx & (H_ - 1));
    const size_t m = idx >> 11;

    const float4 g1 = *(const float4*)(g_gates + m * TWOH + n);
    const float4 g2 = *(const float4*)(g_gates + m * TWOH + H_ + n);
    const float4 mv = *(const float4*)(g_merge + idx);
    const float4 v1 = *(const float4*)(b1 + n);
    const float4 v2 = *(const float4*)(b2 + n);

    float4 r;
    {
        const float st = tanhf(g1.x + v1.x);
        const float u = 1.0f / (1.0f + __expf(-(g2.x + v2.x)));
        r.x = u * st + (1.0f - u) * mv.x;
    }
    {
        const float st = tanhf(g1.y + v1.y);
        const float u = 1.0f / (1.0f + __expf(-(g2.y + v2.y)));
        r.y = u * st + (1.0f - u) * mv.y;
    }
    {
        const float st = tanhf(g1.z + v1.z);
        const float u = 1.0f / (1.0f + __expf(-(g2.z + v2.z)));
        r.z = u * st + (1.0f - u) * mv.z;
    }
    {
        const float st = tanhf(g1.w + v1.w);
        const float u = 1.0f / (1.0f + __expf(-(g2.w + v2.w)));
        r.w = u * st + (1.0f - u) * mv.w;
    }

    *(float4*)(out + idx) = r;
    *(float4*)(out + idx + (size_t)B_ * H_) = r;
}

// ===========================================================================
extern "C" void kernel_launch(void* const* d_in, const int* in_sizes, int n_in,
                              void* d_out, int out_size)
{
    const float* x0 = (const float*)d_in[0];
    const float* x1 = (const float*)d_in[1];
    const float* h0 = (const float*)d_in[2];
    const float* h1 = (const float*)d_in[3];
    const float* W1 = (const float*)d_in[4];
    const float* b1 = (const float*)d_in[5];
    const float* W2 = (const float*)d_in[6];
    const float* b2 = (const float*)d_in[7];
    const float* Wm = (const float*)d_in[8];
    float* out = (float*)d_out;

    __half *wh, *wmh, *sh;
    cudaGetSymbolAddress((void**)&wh, g_Wh);
    cudaGetSymbolAddress((void**)&wmh, g_Wmh);
    cudaGetSymbolAddress((void**)&sh, g_sh);

    static bool attr_set = false;
    if (!attr_set) {
        cudaFuncSetAttribute(gates_mma, cudaFuncAttributeMaxDynamicSharedMemorySize, G_SMEM_B);
        cudaFuncSetAttribute(merge_mma, cudaFuncAttributeMaxDynamicSharedMemorySize, M_SMEM_B);
        attr_set = true;
    }

    // pre-pass: fp32 -> fp16 packing (fused concat)
    pack_W <<<65536, 256>>>(W1, W2, wh);
    pack_s <<<8192, 256>>>(h0, h1, sh);
    pack_Wm<<<4096, 256>>>(Wm, wmh);

    gates_mma<<<dim3(32, 32), 256, G_SMEM_B>>>(wh, sh, x0, x1);
    merge_mma<<<dim3(32, 16), 256, M_SMEM_B>>>(wmh, sh);

    epilogue_kernel<<<(unsigned)((size_t)B_ * H_ / 4 / 256), 256>>>(b1, b2, out);
}

// round 7
// speedup vs baseline: 9.0740x; 1.5096x over previous
#include <cuda_runtime.h>
#include <cuda_fp16.h>
#include <cstdint>

#define B_    4096
#define H_    2048
#define TWOH  4096

// ---------------- device scratch ----------------
__device__ __half g_Wh[(size_t)8 * TWOH * TWOH];   // [8][4096 j][4096 n] (W1 | W2 on n)
__device__ __half g_Wmh[(size_t)TWOH * H_];        // [4096 j][2048 n]
__device__ __half g_sh[(size_t)B_ * TWOH];         // [4096 m][4096 j]  (h0 | h1 on j)
__device__ float  g_gates[(size_t)B_ * TWOH];      // [B][4096] g1 | g2
__device__ float  g_merge[(size_t)B_ * H_];

// ---------------- helpers ----------------
__device__ __forceinline__ uint32_t smem_u32(const void* p) {
    uint32_t a;
    asm("{ .reg .u64 t; cvta.to.shared.u64 t, %1; cvt.u32.u64 %0, t; }" : "=r"(a) : "l"(p));
    return a;
}
__device__ __forceinline__ void cpa16(uint32_t dst, const void* src) {
    asm volatile("cp.async.cg.shared.global [%0], [%1], 16;" :: "r"(dst), "l"(src));
}
#define CP_COMMIT() asm volatile("cp.async.commit_group;")
#define CP_WAIT2()  asm volatile("cp.async.wait_group 2;")
#define CP_WAIT0()  asm volatile("cp.async.wait_group 0;")

__device__ __forceinline__ uint32_t pk2h(float hi, float lo) {
    uint32_t d; asm("cvt.rn.f16x2.f32 %0, %1, %2;" : "=r"(d) : "f"(hi), "f"(lo)); return d;
}
__device__ __forceinline__ uint32_t hmul2(uint32_t a, uint32_t b) {
    uint32_t d; asm("mul.rn.f16x2 %0, %1, %2;" : "=r"(d) : "r"(a), "r"(b)); return d;
}
__device__ __forceinline__ void ldsm4(uint32_t& r0, uint32_t& r1, uint32_t& r2, uint32_t& r3,
                                      uint32_t addr) {
    asm volatile("ldmatrix.sync.aligned.m8n8.x4.shared.b16 {%0,%1,%2,%3}, [%4];"
                 : "=r"(r0), "=r"(r1), "=r"(r2), "=r"(r3) : "r"(addr));
}
__device__ __forceinline__ void ldsm4t(uint32_t& r0, uint32_t& r1, uint32_t& r2, uint32_t& r3,
                                       uint32_t addr) {
    asm volatile("ldmatrix.sync.aligned.m8n8.x4.trans.shared.b16 {%0,%1,%2,%3}, [%4];"
                 : "=r"(r0), "=r"(r1), "=r"(r2), "=r"(r3) : "r"(addr));
}
__device__ __forceinline__ void mma16(float* c, const uint32_t* a, const uint32_t* b) {
    asm volatile(
        "mma.sync.aligned.m16n8k16.row.col.f32.f16.f16.f32 "
        "{%0,%1,%2,%3}, {%4,%5,%6,%7}, {%8,%9}, {%0,%1,%2,%3};"
        : "+f"(c[0]), "+f"(c[1]), "+f"(c[2]), "+f"(c[3])
        : "r"(a[0]), "r"(a[1]), "r"(a[2]), "r"(a[3]), "r"(b[0]), "r"(b[1]));
}

// ---------------- pack kernels (fp32 -> fp16, fused concat) ----------------
__global__ __launch_bounds__(256) void pack_W(const float* __restrict__ W1,
                                              const float* __restrict__ W2,
                                              __half* __restrict__ dst) {
    const size_t idx = ((size_t)blockIdx.x * 256 + threadIdx.x) * 8;
    const int ng = (int)(idx & (TWOH - 1));
    const size_t ij = idx >> 12;
    const float* src = (ng < H_) ? (W1 + ij * H_ + ng) : (W2 + ij * H_ + (ng - H_));
    const float4 v0 = *(const float4*)src;
    const float4 v1 = *(const float4*)(src + 4);
    uint4 o;
    o.x = pk2h(v0.y, v0.x); o.y = pk2h(v0.w, v0.z);
    o.z = pk2h(v1.y, v1.x); o.w = pk2h(v1.w, v1.z);
    *(uint4*)(dst + idx) = o;
}
__global__ __launch_bounds__(256) void pack_s(const float* __restrict__ h0,
                                              const float* __restrict__ h1,
                                              __half* __restrict__ dst) {
    const size_t idx = ((size_t)blockIdx.x * 256 + threadIdx.x) * 8;
    const int j = (int)(idx & (TWOH - 1));
    const size_t m = idx >> 12;
    const float* src = (j < H_) ? (h0 + m * H_ + j) : (h1 + m * H_ + (j - H_));
    const float4 v0 = *(const float4*)src;
    const float4 v1 = *(const float4*)(src + 4);
    uint4 o;
    o.x = pk2h(v0.y, v0.x); o.y = pk2h(v0.w, v0.z);
    o.z = pk2h(v1.y, v1.x); o.w = pk2h(v1.w, v1.z);
    *(uint4*)(dst + idx) = o;
}
__global__ __launch_bounds__(256) void pack_Wm(const float* __restrict__ src,
                                               __half* __restrict__ dst) {
    const size_t idx = ((size_t)blockIdx.x * 256 + threadIdx.x) * 8;
    const float4 v0 = *(const float4*)(src + idx);
    const float4 v1 = *(const float4*)(src + idx + 4);
    uint4 o;
    o.x = pk2h(v0.y, v0.x); o.y = pk2h(v0.w, v0.z);
    o.z = pk2h(v1.y, v1.x); o.w = pk2h(v1.w, v1.z);
    *(uint4*)(dst + idx) = o;
}

// ---------------- smem layout ----------------
// gates: A 2 stages x [128 rows x 40 halfs]; B 4 stages x [64 k x 136 halfs]; xd [128x9] words
#define GA_ROW    40
#define GA_STG    (128 * GA_ROW)            // 5120 halfs
#define GB_ROW    136
#define GB_STG    (64 * GB_ROW)             // 8704 halfs (17408 B)
#define GB_OFF_B  (2 * GA_STG * 2)          // 20480 bytes
#define GXD_OFF_W ((GB_OFF_B + 4 * GB_STG * 2) / 4)
#define G_SMEM_B  (GB_OFF_B + 4 * GB_STG * 2 + 128 * 9 * 4)   // 94720
// merge (unchanged round-6 layout): A 4 stages + B(32k) 4 stages
#define MB_STG    (32 * GB_ROW)             // 4352 halfs
#define MB_OFF_B  (4 * GA_STG * 2)          // 40960 bytes
#define M_SMEM_B  (MB_OFF_B + 4 * MB_STG * 2)  // 75776

// ===========================================================================
// Gates GEMM: C[4096,4096] fp16 MMA, CTA 128m x 128n, 256 thr, 2 CTA/SM.
// 512 sync steps, K=64 per step (two i-slabs per B stage).
// ===========================================================================
__global__ __launch_bounds__(256, 2) void gates_mma(
    const __half* __restrict__ Wh, const __half* __restrict__ sh,
    const float* __restrict__ x0, const float* __restrict__ x1)
{
    extern __shared__ __align__(16) char smc[];
    uint32_t* usm = (uint32_t*)smc;
    const uint32_t smb = smem_u32(smc);
    const int tid = threadIdx.x, lane = tid & 31, wid = tid >> 5;
    const int m0 = blockIdx.x * 128;   // m fastest -> W dedup in L2
    const int n0 = blockIdx.y * 128;
    const int wm = wid & 3, wn = wid >> 2;
    const int lr = lane >> 2, lc = lane & 3;

    // xd: duplicated half2 x-scales [128 rows][8 i], padded stride 9 words
    for (int idx = tid; idx < 1024; idx += 256) {
        const int row = idx >> 3, i = idx & 7;
        const float v = (i < 4) ? x0[(size_t)(m0 + row) * 4 + i]
                                : x1[(size_t)(m0 + row) * 4 + (i - 4)];
        usm[GXD_OFF_W + row * 9 + i] = pk2h(v, v);
    }

    // B stage covers k=64: rows 0-31 slab i0, rows 32-63 slab i0+1
    auto issue_B = [&](int s) {
        const int jb = s >> 2, i0 = (s & 3) * 2, st = s & 3;
#pragma unroll
        for (int it = 0; it < 4; it++) {
            const int idx = it * 256 + tid, row = idx >> 4, c = idx & 15;
            const int slab = i0 + (row >> 5), jr = jb * 32 + (row & 31);
            cpa16(smb + GB_OFF_B + (uint32_t)(st * GB_STG + row * GB_ROW + c * 8) * 2,
                  Wh + ((size_t)slab * TWOH + jr) * TWOH + n0 + c * 8);
        }
    };
    auto issue_A = [&](int jb) {
#pragma unroll
        for (int it = 0; it < 2; it++) {
            const int idx = it * 256 + tid, row = idx >> 2, c = idx & 3;
            cpa16(smb + (uint32_t)(((jb & 1) * 128 + row) * GA_ROW + c * 8) * 2,
                  sh + (size_t)(m0 + row) * TWOH + jb * 32 + c * 8);
        }
    };

    // prologue: 3 groups
    issue_A(0); issue_B(0); CP_COMMIT();
    issue_B(1); CP_COMMIT();
    issue_B(2); CP_COMMIT();

    float acc[2][8][4];
#pragma unroll
    for (int mt = 0; mt < 2; mt++)
#pragma unroll
        for (int nt = 0; nt < 8; nt++)
#pragma unroll
            for (int q = 0; q < 4; q++) acc[mt][nt][q] = 0.f;

    uint32_t areg[2][2][4];   // [mt][ks][frag], reused across all 8 i-steps of jb
    const uint32_t a_lane_off = (uint32_t)(lane & 15) * (GA_ROW * 2) +
                                ((lane >> 4) & 1) * 16;
    const uint32_t b_lane_off = (uint32_t)(lane & 15) * (GB_ROW * 2) +
                                (uint32_t)(wn * 64 + ((lane >> 4) << 3)) * 2;

    for (int s = 0; s < 512; s++) {
        const int jb = s >> 2, q = s & 3, i0 = q * 2;

        if (s >= 509) { CP_WAIT0(); } else { CP_WAIT2(); }
        __syncthreads();

        if (q == 0) {
            const uint32_t ab = smb + (uint32_t)((jb & 1) * 128 + wm * 32) * (GA_ROW * 2);
#pragma unroll
            for (int mt = 0; mt < 2; mt++)
#pragma unroll
                for (int ks = 0; ks < 2; ks++)
                    ldsm4(areg[mt][ks][0], areg[mt][ks][1], areg[mt][ks][2], areg[mt][ks][3],
                          ab + (uint32_t)mt * 16 * (GA_ROW * 2) + a_lane_off + ks * 32);
        }

        // x-scales for the two i's of this step
        uint32_t xd[2][4];
#pragma unroll
        for (int h = 0; h < 2; h++)
#pragma unroll
            for (int mt = 0; mt < 2; mt++) {
                xd[h][mt * 2]     = usm[GXD_OFF_W + (wm * 32 + mt * 16 + lr) * 9 + i0 + h];
                xd[h][mt * 2 + 1] = usm[GXD_OFF_W + (wm * 32 + mt * 16 + 8 + lr) * 9 + i0 + h];
            }

        const uint32_t bb = smb + GB_OFF_B + (uint32_t)(s & 3) * (GB_STG * 2);
#pragma unroll
        for (int h = 0; h < 2; h++) {
            const uint32_t bh = bb + (uint32_t)h * 32 * (GB_ROW * 2);
#pragma unroll
            for (int ks = 0; ks < 2; ks++) {
                uint32_t bfr[8][2];
#pragma unroll
                for (int p = 0; p < 4; p++) {
                    uint32_t r0, r1, r2, r3;
                    ldsm4t(r0, r1, r2, r3,
                           bh + (uint32_t)ks * 16 * (GB_ROW * 2) + b_lane_off + p * 32);
                    bfr[2 * p][0] = r0; bfr[2 * p][1] = r1;
                    bfr[2 * p + 1][0] = r2; bfr[2 * p + 1][1] = r3;
                }
#pragma unroll
                for (int mt = 0; mt < 2; mt++) {
                    uint32_t a[4];
                    a[0] = hmul2(areg[mt][ks][0], xd[h][2 * mt]);
                    a[1] = hmul2(areg[mt][ks][1], xd[h][2 * mt + 1]);
                    a[2] = hmul2(areg[mt][ks][2], xd[h][2 * mt]);
                    a[3] = hmul2(areg[mt][ks][3], xd[h][2 * mt + 1]);
#pragma unroll
                    for (int nt = 0; nt < 8; nt++) mma16(acc[mt][nt], a, bfr[nt]);
                }
            }
        }

        if (s + 3 < 512) {
            issue_B(s + 3);
            if (q == 0 && jb + 1 < 128) issue_A(jb + 1);   // retires >=4 groups before use
            CP_COMMIT();
        }
    }

#pragma unroll
    for (int mt = 0; mt < 2; mt++) {
        const int rg = m0 + wm * 32 + mt * 16 + lr;
#pragma unroll
        for (int nt = 0; nt < 8; nt++) {
            const int cg = n0 + wn * 64 + nt * 8 + 2 * lc;
            *(float2*)(g_gates + (size_t)rg * TWOH + cg) =
                make_float2(acc[mt][nt][0], acc[mt][nt][1]);
            *(float2*)(g_gates + (size_t)(rg + 8) * TWOH + cg) =
                make_float2(acc[mt][nt][2], acc[mt][nt][3]);
        }
    }
}

// ===========================================================================
// Merge GEMM: C[4096,2048] = s @ Wmerge, fp16 MMA, CTA 128x128 (round-6 form).
// ===========================================================================
__global__ __launch_bounds__(256, 2) void merge_mma(
    const __half* __restrict__ Wmh, const __half* __restrict__ sh)
{
    extern __shared__ __align__(16) char smc[];
    const uint32_t smb = smem_u32(smc);
    const int tid = threadIdx.x, lane = tid & 31, wid = tid >> 5;
    const int m0 = blockIdx.x * 128;
    const int n0 = blockIdx.y * 128;
    const int wm = wid & 3, wn = wid >> 2;
    const int lr = lane >> 2, lc = lane & 3;

    auto issue_AB = [&](int s) {
        const int st = s & 3;
#pragma unroll
        for (int it = 0; it < 2; it++) {
            const int idx = it * 256 + tid, row = idx >> 2, c = idx & 3;
            cpa16(smb + (uint32_t)((st * 128 + row) * GA_ROW + c * 8) * 2,
                  sh + (size_t)(m0 + row) * TWOH + s * 32 + c * 8);
        }
#pragma unroll
        for (int it = 0; it < 2; it++) {
            const int idx = it * 256 + tid, row = idx >> 4, c = idx & 15;
            cpa16(smb + MB_OFF_B + (uint32_t)(st * MB_STG + row * GB_ROW + c * 8) * 2,
                  Wmh + (size_t)(s * 32 + row) * H_ + n0 + c * 8);
        }
    };

    issue_AB(0); CP_COMMIT();
    issue_AB(1); CP_COMMIT();
    issue_AB(2); CP_COMMIT();

    float acc[2][8][4];
#pragma unroll
    for (int mt = 0; mt < 2; mt++)
#pragma unroll
        for (int nt = 0; nt < 8; nt++)
#pragma unroll
            for (int q = 0; q < 4; q++) acc[mt][nt][q] = 0.f;

    const uint32_t a_lane_off = (uint32_t)(lane & 15) * (GA_ROW * 2) +
                                ((lane >> 4) & 1) * 16;
    const uint32_t b_lane_off = (uint32_t)(lane & 15) * (GB_ROW * 2) +
                                (uint32_t)(wn * 64 + ((lane >> 4) << 3)) * 2;

    for (int s = 0; s < 128; s++) {
        if (s >= 125) { CP_WAIT0(); } else { CP_WAIT2(); }
        __syncthreads();

        uint32_t areg[2][2][4];
        const uint32_t ab = smb + (uint32_t)((s & 3) * 128 + wm * 32) * (GA_ROW * 2);
#pragma unroll
        for (int mt = 0; mt < 2; mt++)
#pragma unroll
            for (int ks = 0; ks < 2; ks++)
                ldsm4(areg[mt][ks][0], areg[mt][ks][1], areg[mt][ks][2], areg[mt][ks][3],
                      ab + (uint32_t)mt * 16 * (GA_ROW * 2) + a_lane_off + ks * 32);

        const uint32_t bb = smb + MB_OFF_B + (uint32_t)(s & 3) * (MB_STG * 2);
#pragma unroll
        for (int ks = 0; ks < 2; ks++) {
            uint32_t bfr[8][2];
#pragma unroll
            for (int p = 0; p < 4; p++) {
                uint32_t r0, r1, r2, r3;
                ldsm4t(r0, r1, r2, r3,
                       bb + (uint32_t)ks * 16 * (GB_ROW * 2) + b_lane_off + p * 32);
                bfr[2 * p][0] = r0; bfr[2 * p][1] = r1;
                bfr[2 * p + 1][0] = r2; bfr[2 * p + 1][1] = r3;
            }
#pragma unroll
            for (int mt = 0; mt < 2; mt++)
#pragma unroll
                for (int nt = 0; nt < 8; nt++)
                    mma16(acc[mt][nt], areg[mt][ks], bfr[nt]);
        }

        if (s + 3 < 128) { issue_AB(s + 3); CP_COMMIT(); }
    }

#pragma unroll
    for (int mt = 0; mt < 2; mt++) {
        const int rg = m0 + wm * 32 + mt * 16 + lr;
#pragma unroll
        for (int nt = 0; nt < 8; nt++) {
            const int cg = n0 + wn * 64 + nt * 8 + 2 * lc;
            *(float2*)(g_merge + (size_t)rg * H_ + cg) =
                make_float2(acc[mt][nt][0], acc[mt][nt][1]);
            *(float2*)(g_merge + (size_t)(rg + 8) * H_ + cg) =
                make_float2(acc[mt][nt][2], acc[mt][nt][3]);
        }
    }
}

// ===========================================================================
// Epilogue (vectorized)
// ===========================================================================
__global__ __launch_bounds__(256) void epilogue_kernel(
    const float* __restrict__ b1, const float* __restrict__ b2,
    float* __restrict__ out)
{
    const size_t idx = ((size_t)blockIdx.x * 256 + threadIdx.x) * 4;
    const int n = (int)(idx & (H_ - 1));
    const size_t m = idx >> 11;

    const float4 g1 = *(const float4*)(g_gates + m * TWOH + n);
    const float4 g2 = *(const float4*)(g_gates + m * TWOH + H_ + n);
    const float4 mv = *(const float4*)(g_merge + idx);
    const float4 v1 = *(const float4*)(b1 + n);
    const float4 v2 = *(const float4*)(b2 + n);

    float4 r;
    { const float st = tanhf(g1.x + v1.x);
      const float u = 1.0f / (1.0f + __expf(-(g2.x + v2.x)));
      r.x = u * st + (1.0f - u) * mv.x; }
    { const float st = tanhf(g1.y + v1.y);
      const float u = 1.0f / (1.0f + __expf(-(g2.y + v2.y)));
      r.y = u * st + (1.0f - u) * mv.y; }
    { const float st = tanhf(g1.z + v1.z);
      const float u = 1.0f / (1.0f + __expf(-(g2.z + v2.z)));
      r.z = u * st + (1.0f - u) * mv.z; }
    { const float st = tanhf(g1.w + v1.w);
      const float u = 1.0f / (1.0f + __expf(-(g2.w + v2.w)));
      r.w = u * st + (1.0f - u) * mv.w; }

    *(float4*)(out + idx) = r;
    *(float4*)(out + idx + (size_t)B_ * H_) = r;
}

// ===========================================================================
extern "C" void kernel_launch(void* const* d_in, const int* in_sizes, int n_in,
                              void* d_out, int out_size)
{
    const float* x0 = (const float*)d_in[0];
    const float* x1 = (const float*)d_in[1];
    const float* h0 = (const float*)d_in[2];
    const float* h1 = (const float*)d_in[3];
    const float* W1 = (const float*)d_in[4];
    const float* b1 = (const float*)d_in[5];
    const float* W2 = (const float*)d_in[6];
    const float* b2 = (const float*)d_in[7];
    const float* Wm = (const float*)d_in[8];
    float* out = (float*)d_out;

    __half *wh, *wmh, *sh;
    cudaGetSymbolAddress((void**)&wh, g_Wh);
    cudaGetSymbolAddress((void**)&wmh, g_Wmh);
    cudaGetSymbolAddress((void**)&sh, g_sh);

    static bool attr_set = false;
    if (!attr_set) {
        cudaFuncSetAttribute(gates_mma, cudaFuncAttributeMaxDynamicSharedMemorySize, G_SMEM_B);
        cudaFuncSetAttribute(merge_mma, cudaFuncAttributeMaxDynamicSharedMemorySize, M_SMEM_B);
        attr_set = true;
    }

    pack_W <<<65536, 256>>>(W1, W2, wh);
    pack_s <<<8192, 256>>>(h0, h1, sh);
    pack_Wm<<<4096, 256>>>(Wm, wmh);

    gates_mma<<<dim3(32, 32), 256, G_SMEM_B>>>(wh, sh, x0, x1);
    merge_mma<<<dim3(32, 16), 256, M_SMEM_B>>>(wmh, sh);

    epilogue_kernel<<<(unsigned)((size_t)B_ * H_ / 4 / 256), 256>>>(b1, b2, out);
}

// round 8
// speedup vs baseline: 9.1121x; 1.0042x over previous
#include <cuda_runtime.h>
#include <cuda_fp16.h>
#include <cstdint>

#define B_    4096
#define H_    2048
#define TWOH  4096

// ---------------- device scratch ----------------
__device__ __half g_Wh[(size_t)8 * TWOH * TWOH];   // [8][4096 j][4096 n] (W1 | W2 on n)
__device__ __half g_Wmh[(size_t)TWOH * H_];        // [4096 j][2048 n]
__device__ __half g_sh[(size_t)B_ * TWOH];         // [4096 m][4096 j]  (h0 | h1 on j)
__device__ float  g_gates[(size_t)B_ * TWOH];      // [B][4096] g1 | g2
__device__ float  g_merge[(size_t)B_ * H_];

// ---------------- helpers ----------------
__device__ __forceinline__ uint32_t smem_u32(const void* p) {
    uint32_t a;
    asm("{ .reg .u64 t; cvta.to.shared.u64 t, %1; cvt.u32.u64 %0, t; }" : "=r"(a) : "l"(p));
    return a;
}
__device__ __forceinline__ void cpa16(uint32_t dst, const void* src) {
    asm volatile("cp.async.cg.shared.global [%0], [%1], 16;" :: "r"(dst), "l"(src));
}
#define CP_COMMIT() asm volatile("cp.async.commit_group;")
#define CP_WAIT2()  asm volatile("cp.async.wait_group 2;")
#define CP_WAIT0()  asm volatile("cp.async.wait_group 0;")

__device__ __forceinline__ uint32_t pk2h(float hi, float lo) {
    uint32_t d; asm("cvt.rn.f16x2.f32 %0, %1, %2;" : "=r"(d) : "f"(hi), "f"(lo)); return d;
}
__device__ __forceinline__ uint32_t hmul2(uint32_t a, uint32_t b) {
    uint32_t d; asm("mul.rn.f16x2 %0, %1, %2;" : "=r"(d) : "r"(a), "r"(b)); return d;
}
__device__ __forceinline__ void ldsm4(uint32_t& r0, uint32_t& r1, uint32_t& r2, uint32_t& r3,
                                      uint32_t addr) {
    asm volatile("ldmatrix.sync.aligned.m8n8.x4.shared.b16 {%0,%1,%2,%3}, [%4];"
                 : "=r"(r0), "=r"(r1), "=r"(r2), "=r"(r3) : "r"(addr));
}
__device__ __forceinline__ void ldsm4t(uint32_t& r0, uint32_t& r1, uint32_t& r2, uint32_t& r3,
                                       uint32_t addr) {
    asm volatile("ldmatrix.sync.aligned.m8n8.x4.trans.shared.b16 {%0,%1,%2,%3}, [%4];"
                 : "=r"(r0), "=r"(r1), "=r"(r2), "=r"(r3) : "r"(addr));
}
__device__ __forceinline__ void mma16(float* c, const uint32_t* a, const uint32_t* b) {
    asm volatile(
        "mma.sync.aligned.m16n8k16.row.col.f32.f16.f16.f32 "
        "{%0,%1,%2,%3}, {%4,%5,%6,%7}, {%8,%9}, {%0,%1,%2,%3};"
        : "+f"(c[0]), "+f"(c[1]), "+f"(c[2]), "+f"(c[3])
        : "r"(a[0]), "r"(a[1]), "r"(a[2]), "r"(a[3]), "r"(b[0]), "r"(b[1]));
}

// ---------------- pack kernels (fp32 -> fp16, fused concat) ----------------
__global__ __launch_bounds__(256) void pack_W(const float* __restrict__ W1,
                                              const float* __restrict__ W2,
                                              __half* __restrict__ dst) {
    const size_t idx = ((size_t)blockIdx.x * 256 + threadIdx.x) * 8;
    const int ng = (int)(idx & (TWOH - 1));
    const size_t ij = idx >> 12;
    const float* src = (ng < H_) ? (W1 + ij * H_ + ng) : (W2 + ij * H_ + (ng - H_));
    const float4 v0 = *(const float4*)src;
    const float4 v1 = *(const float4*)(src + 4);
    uint4 o;
    o.x = pk2h(v0.y, v0.x); o.y = pk2h(v0.w, v0.z);
    o.z = pk2h(v1.y, v1.x); o.w = pk2h(v1.w, v1.z);
    *(uint4*)(dst + idx) = o;
}
__global__ __launch_bounds__(256) void pack_s(const float* __restrict__ h0,
                                              const float* __restrict__ h1,
                                              __half* __restrict__ dst) {
    const size_t idx = ((size_t)blockIdx.x * 256 + threadIdx.x) * 8;
    const int j = (int)(idx & (TWOH - 1));
    const size_t m = idx >> 12;
    const float* src = (j < H_) ? (h0 + m * H_ + j) : (h1 + m * H_ + (j - H_));
    const float4 v0 = *(const float4*)src;
    const float4 v1 = *(const float4*)(src + 4);
    uint4 o;
    o.x = pk2h(v0.y, v0.x); o.y = pk2h(v0.w, v0.z);
    o.z = pk2h(v1.y, v1.x); o.w = pk2h(v1.w, v1.z);
    *(uint4*)(dst + idx) = o;
}
__global__ __launch_bounds__(256) void pack_Wm(const float* __restrict__ src,
                                               __half* __restrict__ dst) {
    const size_t idx = ((size_t)blockIdx.x * 256 + threadIdx.x) * 8;
    const float4 v0 = *(const float4*)(src + idx);
    const float4 v1 = *(const float4*)(src + idx + 4);
    uint4 o;
    o.x = pk2h(v0.y, v0.x); o.y = pk2h(v0.w, v0.z);
    o.z = pk2h(v1.y, v1.x); o.w = pk2h(v1.w, v1.z);
    *(uint4*)(dst + idx) = o;
}

// ---------------- smem layout ----------------
#define GA_ROW    40
#define GA_STG    (128 * GA_ROW)            // 5120 halfs (10240 B)
#define GB_ROW    136
// gates: A 2 stg; B 2 stg x [128 k x 136 halfs]; xd [128x9] words
#define GB_STG    (128 * GB_ROW)            // 17408 halfs (34816 B)
#define GB_OFF_B  (2 * GA_STG * 2)          // 20480 bytes
#define GXD_OFF_W ((GB_OFF_B + 2 * GB_STG * 2) / 4)   // 22528
#define G_SMEM_B  (GB_OFF_B + 2 * GB_STG * 2 + 128 * 9 * 4)   // 94720
// merge: A 4 stg x GA_STG ; B 4 stg x [32 k x 136]
#define MB_STG    (32 * GB_ROW)             // 4352 halfs
#define MB_OFF_B  (4 * GA_STG * 2)          // 40960 bytes  (< G_SMEM_B budget)

// ===========================================================================
// Fused GEMM kernel. Tiles 0..1023: gates C[4096,4096]; 1024..1535: merge.
// Gates: 256 sync steps, K=128/step (4 i-slabs), 2-stage double buffer.
// Merge tiles are short (1/8 work) and fill the gates tail wave.
// ===========================================================================
__global__ __launch_bounds__(256, 2) void fused_mma(
    const __half* __restrict__ Wh, const __half* __restrict__ Wmh,
    const __half* __restrict__ sh,
    const float* __restrict__ x0, const float* __restrict__ x1)
{
    extern __shared__ __align__(16) char smc[];
    uint32_t* usm = (uint32_t*)smc;
    const uint32_t smb = smem_u32(smc);
    const int tid = threadIdx.x, lane = tid & 31, wid = tid >> 5;
    const int wm = wid & 3, wn = wid >> 2;
    const int lr = lane >> 2, lc = lane & 3;
    const int tile = blockIdx.x;

    const uint32_t a_lane_off = (uint32_t)(lane & 15) * (GA_ROW * 2) +
                                ((lane >> 4) & 1) * 16;
    const uint32_t b_lane_off = (uint32_t)(lane & 15) * (GB_ROW * 2) +
                                (uint32_t)(wn * 64 + ((lane >> 4) << 3)) * 2;

    float acc[2][8][4];
#pragma unroll
    for (int mt = 0; mt < 2; mt++)
#pragma unroll
        for (int nt = 0; nt < 8; nt++)
#pragma unroll
            for (int q = 0; q < 4; q++) acc[mt][nt][q] = 0.f;

    if (tile < 1024) {
        // ================= gates path =================
        const int m0 = (tile & 31) * 128;       // m fastest -> W dedup in L2
        const int n0 = (tile >> 5) * 128;

        // xd: duplicated half2 x-scales [128 rows][8 i], stride 9 words
        for (int idx = tid; idx < 1024; idx += 256) {
            const int row = idx >> 3, i = idx & 7;
            const float v = (i < 4) ? x0[(size_t)(m0 + row) * 4 + i]
                                    : x1[(size_t)(m0 + row) * 4 + (i - 4)];
            usm[GXD_OFF_W + row * 9 + i] = pk2h(v, v);
        }

        // B stage: 128 k-rows = 4 i-slabs x 32 j ; step s -> jb=s>>1, q=s&1
        auto issue_B = [&](int s) {
            const int jb = s >> 1, q = s & 1, st = s & 1;
#pragma unroll
            for (int it = 0; it < 8; it++) {
                const int idx = it * 256 + tid, row = idx >> 4, c = idx & 15;
                const int slab = q * 4 + (row >> 5), jr = jb * 32 + (row & 31);
                cpa16(smb + GB_OFF_B + (uint32_t)(st * GB_STG + row * GB_ROW + c * 8) * 2,
                      Wh + ((size_t)slab * TWOH + jr) * TWOH + n0 + c * 8);
            }
        };
        auto issue_A = [&](int jb) {
#pragma unroll
            for (int it = 0; it < 2; it++) {
                const int idx = it * 256 + tid, row = idx >> 2, c = idx & 3;
                cpa16(smb + (uint32_t)(((jb & 1) * 128 + row) * GA_ROW + c * 8) * 2,
                      sh + (size_t)(m0 + row) * TWOH + jb * 32 + c * 8);
            }
        };

        // prologue: stage 0 (A(0) + B(0))
        issue_A(0); issue_B(0); CP_COMMIT();

        uint32_t areg[2][2][4];   // [mt][ks], reused for the 2 steps of each jb

        for (int s = 0; s < 256; s++) {
            const int jb = s >> 1, q = s & 1;

            CP_WAIT0();          // stage for step s (and any A) landed
            __syncthreads();     // all warps done reading the other stage

            if (s + 1 < 256) {
                issue_B(s + 1);
                if (q == 0 && jb + 1 < 128) issue_A(jb + 1);
                CP_COMMIT();
            }

            if (q == 0) {
                const uint32_t ab = smb +
                    (uint32_t)((jb & 1) * 128 + wm * 32) * (GA_ROW * 2);
#pragma unroll
                for (int mt = 0; mt < 2; mt++)
#pragma unroll
                    for (int ks = 0; ks < 2; ks++)
                        ldsm4(areg[mt][ks][0], areg[mt][ks][1],
                              areg[mt][ks][2], areg[mt][ks][3],
                              ab + (uint32_t)mt * 16 * (GA_ROW * 2) + a_lane_off + ks * 32);
            }

            const uint32_t bb = smb + GB_OFF_B + (uint32_t)(s & 1) * (GB_STG * 2);
#pragma unroll
            for (int h = 0; h < 4; h++) {
                const int i = q * 4 + h;
                uint32_t xd0 = usm[GXD_OFF_W + (wm * 32 + lr) * 9 + i];
                uint32_t xd1 = usm[GXD_OFF_W + (wm * 32 + 8 + lr) * 9 + i];
                uint32_t xd2 = usm[GXD_OFF_W + (wm * 32 + 16 + lr) * 9 + i];
                uint32_t xd3 = usm[GXD_OFF_W + (wm * 32 + 24 + lr) * 9 + i];
                const uint32_t bh = bb + (uint32_t)h * 32 * (GB_ROW * 2);
#pragma unroll
                for (int ks = 0; ks < 2; ks++) {
                    uint32_t bfr[8][2];
#pragma unroll
                    for (int p = 0; p < 4; p++) {
                        uint32_t r0, r1, r2, r3;
                        ldsm4t(r0, r1, r2, r3,
                               bh + (uint32_t)ks * 16 * (GB_ROW * 2) + b_lane_off + p * 32);
                        bfr[2 * p][0] = r0; bfr[2 * p][1] = r1;
                        bfr[2 * p + 1][0] = r2; bfr[2 * p + 1][1] = r3;
                    }
#pragma unroll
                    for (int mt = 0; mt < 2; mt++) {
                        uint32_t a[4];
                        const uint32_t xlo = (mt == 0) ? xd0 : xd2;
                        const uint32_t xhi = (mt == 0) ? xd1 : xd3;
                        a[0] = hmul2(areg[mt][ks][0], xlo);
                        a[1] = hmul2(areg[mt][ks][1], xhi);
                        a[2] = hmul2(areg[mt][ks][2], xlo);
                        a[3] = hmul2(areg[mt][ks][3], xhi);
#pragma unroll
                        for (int nt = 0; nt < 8; nt++) mma16(acc[mt][nt], a, bfr[nt]);
                    }
                }
            }
        }

#pragma unroll
        for (int mt = 0; mt < 2; mt++) {
            const int rg = m0 + wm * 32 + mt * 16 + lr;
#pragma unroll
            for (int nt = 0; nt < 8; nt++) {
                const int cg = n0 + wn * 64 + nt * 8 + 2 * lc;
                *(float2*)(g_gates + (size_t)rg * TWOH + cg) =
                    make_float2(acc[mt][nt][0], acc[mt][nt][1]);
                *(float2*)(g_gates + (size_t)(rg + 8) * TWOH + cg) =
                    make_float2(acc[mt][nt][2], acc[mt][nt][3]);
            }
        }
    } else {
        // ================= merge path =================
        const int t = tile - 1024;
        const int m0 = (t & 31) * 128;
        const int n0 = (t >> 5) * 128;

        auto issue_AB = [&](int s) {
            const int st = s & 3;
#pragma unroll
            for (int it = 0; it < 2; it++) {
                const int idx = it * 256 + tid, row = idx >> 2, c = idx & 3;
                cpa16(smb + (uint32_t)((st * 128 + row) * GA_ROW + c * 8) * 2,
                      sh + (size_t)(m0 + row) * TWOH + s * 32 + c * 8);
            }
#pragma unroll
            for (int it = 0; it < 2; it++) {
                const int idx = it * 256 + tid, row = idx >> 4, c = idx & 15;
                cpa16(smb + MB_OFF_B + (uint32_t)(st * MB_STG + row * GB_ROW + c * 8) * 2,
                      Wmh + (size_t)(s * 32 + row) * H_ + n0 + c * 8);
            }
        };

        issue_AB(0); CP_COMMIT();
        issue_AB(1); CP_COMMIT();
        issue_AB(2); CP_COMMIT();

        for (int s = 0; s < 128; s++) {
            if (s >= 125) { CP_WAIT0(); } else { CP_WAIT2(); }
            __syncthreads();

            uint32_t areg[2][2][4];
            const uint32_t ab = smb + (uint32_t)((s & 3) * 128 + wm * 32) * (GA_ROW * 2);
#pragma unroll
            for (int mt = 0; mt < 2; mt++)
#pragma unroll
                for (int ks = 0; ks < 2; ks++)
                    ldsm4(areg[mt][ks][0], areg[mt][ks][1], areg[mt][ks][2], areg[mt][ks][3],
                          ab + (uint32_t)mt * 16 * (GA_ROW * 2) + a_lane_off + ks * 32);

            const uint32_t bb = smb + MB_OFF_B + (uint32_t)(s & 3) * (MB_STG * 2);
#pragma unroll
            for (int ks = 0; ks < 2; ks++) {
                uint32_t bfr[8][2];
#pragma unroll
                for (int p = 0; p < 4; p++) {
                    uint32_t r0, r1, r2, r3;
                    ldsm4t(r0, r1, r2, r3,
                           bb + (uint32_t)ks * 16 * (GB_ROW * 2) + b_lane_off + p * 32);
                    bfr[2 * p][0] = r0; bfr[2 * p][1] = r1;
                    bfr[2 * p + 1][0] = r2; bfr[2 * p + 1][1] = r3;
                }
#pragma unroll
                for (int mt = 0; mt < 2; mt++)
#pragma unroll
                    for (int nt = 0; nt < 8; nt++)
                        mma16(acc[mt][nt], areg[mt][ks], bfr[nt]);
            }

            if (s + 3 < 128) { issue_AB(s + 3); CP_COMMIT(); }
        }

#pragma unroll
        for (int mt = 0; mt < 2; mt++) {
            const int rg = m0 + wm * 32 + mt * 16 + lr;
#pragma unroll
            for (int nt = 0; nt < 8; nt++) {
                const int cg = n0 + wn * 64 + nt * 8 + 2 * lc;
                *(float2*)(g_merge + (size_t)rg * H_ + cg) =
                    make_float2(acc[mt][nt][0], acc[mt][nt][1]);
                *(float2*)(g_merge + (size_t)(rg + 8) * H_ + cg) =
                    make_float2(acc[mt][nt][2], acc[mt][nt][3]);
            }
        }
    }
}

// ===========================================================================
// Epilogue (vectorized)
// ===========================================================================
__global__ __launch_bounds__(256) void epilogue_kernel(
    const float* __restrict__ b1, const float* __restrict__ b2,
    float* __restrict__ out)
{
    const size_t idx = ((size_t)blockIdx.x * 256 + threadIdx.x) * 4;
    const int n = (int)(idx & (H_ - 1));
    const size_t m = idx >> 11;

    const float4 g1 = *(const float4*)(g_gates + m * TWOH + n);
    const float4 g2 = *(const float4*)(g_gates + m * TWOH + H_ + n);
    const float4 mv = *(const float4*)(g_merge + idx);
    const float4 v1 = *(const float4*)(b1 + n);
    const float4 v2 = *(const float4*)(b2 + n);

    float4 r;
    { const float st = tanhf(g1.x + v1.x);
      const float u = 1.0f / (1.0f + __expf(-(g2.x + v2.x)));
      r.x = u * st + (1.0f - u) * mv.x; }
    { const float st = tanhf(g1.y + v1.y);
      const float u = 1.0f / (1.0f + __expf(-(g2.y + v2.y)));
      r.y = u * st + (1.0f - u) * mv.y; }
    { const float st = tanhf(g1.z + v1.z);
      const float u = 1.0f / (1.0f + __expf(-(g2.z + v2.z)));
      r.z = u * st + (1.0f - u) * mv.z; }
    { const float st = tanhf(g1.w + v1.w);
      const float u = 1.0f / (1.0f + __expf(-(g2.w + v2.w)));
      r.w = u * st + (1.0f - u) * mv.w; }

    *(float4*)(out + idx) = r;
    *(float4*)(out + idx + (size_t)B_ * H_) = r;
}

// ===========================================================================
extern "C" void kernel_launch(void* const* d_in, const int* in_sizes, int n_in,
                              void* d_out, int out_size)
{
    const float* x0 = (const float*)d_in[0];
    const float* x1 = (const float*)d_in[1];
    const float* h0 = (const float*)d_in[2];
    const float* h1 = (const float*)d_in[3];
    const float* W1 = (const float*)d_in[4];
    const float* b1 = (const float*)d_in[5];
    const float* W2 = (const float*)d_in[6];
    const float* b2 = (const float*)d_in[7];
    const float* Wm = (const float*)d_in[8];
    float* out = (float*)d_out;

    __half *wh, *wmh, *sh;
    cudaGetSymbolAddress((void**)&wh, g_Wh);
    cudaGetSymbolAddress((void**)&wmh, g_Wmh);
    cudaGetSymbolAddress((void**)&sh, g_sh);

    static bool attr_set = false;
    if (!attr_set) {
        cudaFuncSetAttribute(fused_mma, cudaFuncAttributeMaxDynamicSharedMemorySize, G_SMEM_B);
        attr_set = true;
    }

    pack_W <<<65536, 256>>>(W1, W2, wh);
    pack_s <<<8192, 256>>>(h0, h1, sh);
    pack_Wm<<<4096, 256>>>(Wm, wmh);

    fused_mma<<<1536, 256, G_SMEM_B>>>(wh, wmh, sh, x0, x1);

    epilogue_kernel<<<(unsigned)((size_t)B_ * H_ / 4 / 256), 256>>>(b1, b2, out);
}